// round 2
// baseline (speedup 1.0000x reference)
#include <cuda_runtime.h>
#include <math.h>

// ---------------- problem constants ----------------
#define D_MODEL 2048
#define D3      6144      // 3*D
#define DFF     8192      // 4*D
#define TSEQ    1024
#define NBATCH  2
#define NTOK    2048      // B*T
#define NHEAD   16
#define HD      128

// ---------------- scratch (device globals; no allocations allowed) ----------------
static __device__ __align__(128) float g_xn [NTOK * D_MODEL];   // layernorm output (reused)
static __device__ __align__(128) float g_qkv[NTOK * D3];
static __device__ __align__(128) float g_att[NTOK * D_MODEL];   // attention output (pre-proj)
static __device__ __align__(128) float g_x1 [NTOK * D_MODEL];   // x + attn branch
static __device__ __align__(128) float g_h  [NTOK * DFF];       // gelu(fc)

// ---------------- PWL surrogate tables ----------------
static __device__ float g_gx[512], g_gy[512], g_gs[512];   // gelu, uniform [-10,10]
static __device__ float g_ex[512], g_ey[512], g_es[512];   // exp,  uniform [-30,0]
static __device__ float g_ix[512], g_iy[512], g_is[512];   // inv,  geomspace [1e-3,4096]
static __device__ float g_rx[512], g_ry[512], g_rs[512];   // rsqrt, geomspace [1e-6,100]

__global__ void init_tables_kernel()
{
    int i = threadIdx.x;            // 512 threads
    // gelu grid: linspace(-10,10,512) (float32 knots), y computed per numpy promotion:
    // inner = x + 0.044715*x^3 in float32, outer in float64, cast to float32.
    {
        double t = -10.0 + 20.0 * (double)i / 511.0;
        float x = (float)t;
        g_gx[i] = x;
        float inner = x + 0.044715f * x * x * x;
        double y = 0.5 * (double)x * (1.0 + tanh(0.7978845608028653559 * (double)inner));
        g_gy[i] = (float)y;
    }
    // exp grid: linspace(-30,0,512)
    {
        double t = -30.0 + 30.0 * (double)i / 511.0;
        float x = (float)t;
        g_ex[i] = x;
        g_ey[i] = (float)exp((double)x);
    }
    // inv grid: geomspace(1e-3, 4096) = 10**linspace(-3, log10(4096), 512)
    {
        double lg = -3.0 + (log10(4096.0) + 3.0) * (double)i / 511.0;
        float x = (float)pow(10.0, lg);
        g_ix[i] = x;
        g_iy[i] = 1.0f / x;
    }
    // rsqrt grid: geomspace(1e-6, 100) = 10**linspace(-6, 2, 512)
    {
        double lg = -6.0 + 8.0 * (double)i / 511.0;
        float x = (float)pow(10.0, lg);
        g_rx[i] = x;
        g_ry[i] = 1.0f / sqrtf(x);
    }
    __syncthreads();
    if (i < 511) {
        g_gs[i] = (g_gy[i + 1] - g_gy[i]) / (g_gx[i + 1] - g_gx[i]);
        g_es[i] = (g_ey[i + 1] - g_ey[i]) / (g_ex[i + 1] - g_ex[i]);
        g_is[i] = (g_iy[i + 1] - g_iy[i]) / (g_ix[i + 1] - g_ix[i]);
        g_rs[i] = (g_ry[i + 1] - g_ry[i]) / (g_rx[i + 1] - g_rx[i]);
    }
}

// ---------------- interp helpers (faithful jnp.interp semantics) ----------------
__device__ __forceinline__ float pwl_seg(float x, const float* xp, const float* fp,
                                         const float* sl, int i)
{
    i = min(max(i, 0), 510);
    while (i > 0 && x < xp[i]) --i;
    while (i < 510 && x >= xp[i + 1]) ++i;
    return fp[i] + (x - xp[i]) * sl[i];
}
__device__ __forceinline__ float pwl_gelu_f(float x)
{
    if (x <= g_gx[0])   return g_gy[0];
    if (x >= g_gx[511]) return g_gy[511];
    return pwl_seg(x, g_gx, g_gy, g_gs, (int)((x + 10.0f) * (511.0f / 20.0f)));
}
__device__ __forceinline__ float pwl_exp_f(float x)  // x already clipped to [-30,0]
{
    if (x <= g_ex[0])   return g_ey[0];
    if (x >= g_ex[511]) return g_ey[511];
    return pwl_seg(x, g_ex, g_ey, g_es, (int)((x + 30.0f) * (511.0f / 30.0f)));
}
__device__ __forceinline__ float pwl_inv_f(float x)
{
    if (x <= g_ix[0])   return g_iy[0];
    if (x >= g_ix[511]) return g_iy[511];
    int i = (int)((log2f(x) + 9.965784284662087f) * 23.263455f);
    return pwl_seg(x, g_ix, g_iy, g_is, i);
}
__device__ __forceinline__ float pwl_rsqrt_f(float x)
{
    if (x <= g_rx[0])   return g_ry[0];
    if (x >= g_rx[511]) return g_ry[511];
    int i = (int)((log2f(x) + 19.931568569324174f) * 19.228312f);
    return pwl_seg(x, g_rx, g_ry, g_rs, i);
}

// ---------------- layernorm: one block per row, deterministic tree reduction ----------------
__global__ void __launch_bounds__(256) ln_kernel(const float* __restrict__ x,
                                                 const float* __restrict__ w,
                                                 const float* __restrict__ b,
                                                 float* __restrict__ out)
{
    __shared__ float red[32];
    int row = blockIdx.x, tid = threadIdx.x;
    const float* xr = x + (size_t)row * D_MODEL;
    int base = tid * 8;
    float4 u0 = *(const float4*)(xr + base);
    float4 u1 = *(const float4*)(xr + base + 4);
    float v[8] = {u0.x, u0.y, u0.z, u0.w, u1.x, u1.y, u1.z, u1.w};

    float s = 0.f;
#pragma unroll
    for (int i = 0; i < 8; i++) s += v[i];
#pragma unroll
    for (int o = 16; o; o >>= 1) s += __shfl_xor_sync(0xffffffffu, s, o);
    int lane = tid & 31, wid = tid >> 5;
    if (lane == 0) red[wid] = s;
    __syncthreads();
    if (tid == 0) {
        float t = 0.f;
#pragma unroll
        for (int i = 0; i < 8; i++) t += red[i];
        red[16] = t * (1.0f / 2048.0f);
    }
    __syncthreads();
    float mu = red[16];

    float sq = 0.f;
#pragma unroll
    for (int i = 0; i < 8; i++) { float d = v[i] - mu; sq += d * d; }
#pragma unroll
    for (int o = 16; o; o >>= 1) sq += __shfl_xor_sync(0xffffffffu, sq, o);
    if (lane == 0) red[wid] = sq;
    __syncthreads();
    if (tid == 0) {
        float t = 0.f;
#pragma unroll
        for (int i = 0; i < 8; i++) t += red[i];
        red[17] = pwl_rsqrt_f(t * (1.0f / 2048.0f) + 1e-5f);
    }
    __syncthreads();
    float inv_std = red[17];

    float4 w0 = *(const float4*)(w + base);
    float4 w1 = *(const float4*)(w + base + 4);
    float4 b0 = *(const float4*)(b + base);
    float4 b1 = *(const float4*)(b + base + 4);
    float wv[8] = {w0.x, w0.y, w0.z, w0.w, w1.x, w1.y, w1.z, w1.w};
    float bv[8] = {b0.x, b0.y, b0.z, b0.w, b1.x, b1.y, b1.z, b1.w};
    float r[8];
#pragma unroll
    for (int i = 0; i < 8; i++) r[i] = (v[i] - mu) * inv_std * wv[i] + bv[i];
    float* op = out + (size_t)row * D_MODEL + base;
    *(float4*)(op)     = make_float4(r[0], r[1], r[2], r[3]);
    *(float4*)(op + 4) = make_float4(r[4], r[5], r[6], r[7]);
}

// ---------------- tiled SGEMM, 128x128x16, 8x8 microtile ----------------
// EPI: 0 = bias, 1 = bias + pwl_gelu, 2 = bias + residual
#define ASTR 132
template <int EPI>
__global__ void __launch_bounds__(256) gemm_kernel(const float* __restrict__ A,
                                                   const float* __restrict__ B,
                                                   const float* __restrict__ bias,
                                                   const float* __restrict__ R,
                                                   float* __restrict__ C,
                                                   int M, int N, int K)
{
    __shared__ float As[16 * ASTR];   // transposed A tile [k][m], padded
    __shared__ float Bs[16 * 128];    // B tile [k][n]

    int tid = threadIdx.x;
    int bm = blockIdx.y * 128, bn = blockIdx.x * 128;
    int tx = tid & 15, ty = tid >> 4;
    int cm = ty * 8, cn = tx * 8;

    float acc[8][8];
#pragma unroll
    for (int i = 0; i < 8; i++)
#pragma unroll
        for (int j = 0; j < 8; j++) acc[i][j] = 0.f;

    int arow = tid >> 2, acol = (tid & 3) << 2;   // A: 64 rows x 16 cols per pass
    int brow = tid >> 5, bcol = (tid & 31) << 2;  // B: 8 rows x 128 cols per pass

    const float* Ap0 = A + (size_t)(bm + arow) * K + acol;
    const float* Ap1 = Ap0 + (size_t)64 * K;
    const float* Bp0 = B + (size_t)brow * N + bn + bcol;
    const float* Bp1 = Bp0 + (size_t)8 * N;

    for (int k0 = 0; k0 < K; k0 += 16) {
        float4 a0 = *(const float4*)(Ap0 + k0);
        float4 a1 = *(const float4*)(Ap1 + k0);
        float4 b0 = *(const float4*)(Bp0 + (size_t)k0 * N);
        float4 b1 = *(const float4*)(Bp1 + (size_t)k0 * N);
        __syncthreads();
        As[(acol + 0) * ASTR + arow] = a0.x;
        As[(acol + 1) * ASTR + arow] = a0.y;
        As[(acol + 2) * ASTR + arow] = a0.z;
        As[(acol + 3) * ASTR + arow] = a0.w;
        As[(acol + 0) * ASTR + arow + 64] = a1.x;
        As[(acol + 1) * ASTR + arow + 64] = a1.y;
        As[(acol + 2) * ASTR + arow + 64] = a1.z;
        As[(acol + 3) * ASTR + arow + 64] = a1.w;
        *(float4*)(Bs + brow * 128 + bcol)       = b0;
        *(float4*)(Bs + (brow + 8) * 128 + bcol) = b1;
        __syncthreads();
#pragma unroll
        for (int k = 0; k < 16; k++) {
            float a[8], bb[8];
            *(float4*)(a)      = *(const float4*)(As + k * ASTR + cm);
            *(float4*)(a + 4)  = *(const float4*)(As + k * ASTR + cm + 4);
            *(float4*)(bb)     = *(const float4*)(Bs + k * 128 + cn);
            *(float4*)(bb + 4) = *(const float4*)(Bs + k * 128 + cn + 4);
#pragma unroll
            for (int i = 0; i < 8; i++)
#pragma unroll
                for (int j = 0; j < 8; j++) acc[i][j] += a[i] * bb[j];
        }
    }

#pragma unroll
    for (int i = 0; i < 8; i++) {
        int row = bm + cm + i;
        float r[8];
#pragma unroll
        for (int j = 0; j < 8; j++) {
            int col = bn + cn + j;
            float v = acc[i][j] + bias[col];
            if (EPI == 1) v = pwl_gelu_f(v);
            if (EPI == 2) v += R[(size_t)row * N + col];
            r[j] = v;
        }
        float* cp = C + (size_t)row * N + bn + cn;
        *(float4*)(cp)     = make_float4(r[0], r[1], r[2], r[3]);
        *(float4*)(cp + 4) = make_float4(r[4], r[5], r[6], r[7]);
    }
}

// ---------------- attention: two-pass causal softmax with PWL exp/inv ----------------
// grid: (T/64, NHEAD, NBATCH), 256 threads, dynamic smem.
#define ATT_SMEM_FLOATS (128 * 65 * 2 + 64 * 132 + 64 * 68 + 128)
#define ATT_SMEM_BYTES  (ATT_SMEM_FLOATS * 4)

__global__ void __launch_bounds__(256) attn_kernel(const float* __restrict__ qkv,
                                                   float* __restrict__ att)
{
    extern __shared__ float sm[];
    float* sQt    = sm;                   // [128][65]  q transposed
    float* sKt    = sm + 128 * 65;        // [128][65]  k transposed
    float* sV     = sm + 2 * 128 * 65;    // [64][132]
    float* sE     = sV + 64 * 132;        // [64][68]
    float* rowmax = sE + 64 * 68;         // [64]
    float* rowsum = rowmax + 64;          // [64]

    int tid = threadIdx.x;
    int qt = blockIdx.x, h = blockIdx.y, bb = blockIdx.z;
    int qbase = qt * 64;
    const float scale = 1.0f / sqrtf(128.0f);

    int lr = tid >> 5;           // 0..7
    int lc = (tid & 31) << 2;    // 0..124

    const float* qp = qkv + (size_t)(bb * TSEQ + qbase) * D3 + h * HD;
    const float* kp = qkv + (size_t)(bb * TSEQ) * D3 + D_MODEL + h * HD;
    const float* vp = qkv + (size_t)(bb * TSEQ) * D3 + 2 * D_MODEL + h * HD;

#pragma unroll
    for (int r = lr; r < 64; r += 8) {
        float4 q4 = *(const float4*)(qp + (size_t)r * D3 + lc);
        sQt[(lc + 0) * 65 + r] = q4.x;
        sQt[(lc + 1) * 65 + r] = q4.y;
        sQt[(lc + 2) * 65 + r] = q4.z;
        sQt[(lc + 3) * 65 + r] = q4.w;
    }
    if (tid < 64) { rowmax[tid] = -INFINITY; rowsum[tid] = 0.0f; }

    int tx = tid & 15, ty = tid >> 4;
    int ci = ty * 4, cj = tx * 4;
    int nkt = qt + 1;

    // ---- pass 1: exact row max of scaled, masked scores ----
    for (int kb = 0; kb < nkt; kb++) {
        __syncthreads();
#pragma unroll
        for (int r = lr; r < 64; r += 8) {
            float4 k4 = *(const float4*)(kp + (size_t)(kb * 64 + r) * D3 + lc);
            sKt[(lc + 0) * 65 + r] = k4.x;
            sKt[(lc + 1) * 65 + r] = k4.y;
            sKt[(lc + 2) * 65 + r] = k4.z;
            sKt[(lc + 3) * 65 + r] = k4.w;
        }
        __syncthreads();
        float s[4][4];
#pragma unroll
        for (int u = 0; u < 4; u++)
#pragma unroll
            for (int v = 0; v < 4; v++) s[u][v] = 0.f;
#pragma unroll 8
        for (int d = 0; d < 128; d++) {
            float a0 = sQt[d * 65 + ci + 0], a1 = sQt[d * 65 + ci + 1];
            float a2 = sQt[d * 65 + ci + 2], a3 = sQt[d * 65 + ci + 3];
            float b0 = sKt[d * 65 + cj + 0], b1 = sKt[d * 65 + cj + 1];
            float b2 = sKt[d * 65 + cj + 2], b3 = sKt[d * 65 + cj + 3];
            s[0][0] += a0 * b0; s[0][1] += a0 * b1; s[0][2] += a0 * b2; s[0][3] += a0 * b3;
            s[1][0] += a1 * b0; s[1][1] += a1 * b1; s[1][2] += a1 * b2; s[1][3] += a1 * b3;
            s[2][0] += a2 * b0; s[2][1] += a2 * b1; s[2][2] += a2 * b2; s[2][3] += a2 * b3;
            s[3][0] += a3 * b0; s[3][1] += a3 * b1; s[3][2] += a3 * b2; s[3][3] += a3 * b3;
        }
        bool diag = (kb == qt);
#pragma unroll
        for (int u = 0; u < 4; u++)
#pragma unroll
            for (int v = 0; v < 4; v++) {
                float val = s[u][v] * scale;
                if (diag && (kb * 64 + cj + v > qbase + ci + u)) val = -INFINITY;
                sE[(ci + u) * 68 + cj + v] = val;
            }
        __syncthreads();
        if (tid < 64) {
            float m = rowmax[tid];
            for (int j = 0; j < 64; j++) m = fmaxf(m, sE[tid * 68 + j]);
            rowmax[tid] = m;
        }
    }
    __syncthreads();
    float rm[4];
#pragma unroll
    for (int u = 0; u < 4; u++) rm[u] = rowmax[ci + u];

    // ---- pass 2: e = pwl_exp(clip(s-m)), rowsum, o += e @ V ----
    float o[4][8];
#pragma unroll
    for (int u = 0; u < 4; u++)
#pragma unroll
        for (int j = 0; j < 8; j++) o[u][j] = 0.f;

    for (int kb = 0; kb < nkt; kb++) {
        __syncthreads();
#pragma unroll
        for (int r = lr; r < 64; r += 8) {
            float4 k4 = *(const float4*)(kp + (size_t)(kb * 64 + r) * D3 + lc);
            sKt[(lc + 0) * 65 + r] = k4.x;
            sKt[(lc + 1) * 65 + r] = k4.y;
            sKt[(lc + 2) * 65 + r] = k4.z;
            sKt[(lc + 3) * 65 + r] = k4.w;
            float4 v4 = *(const float4*)(vp + (size_t)(kb * 64 + r) * D3 + lc);
            *(float4*)(sV + r * 132 + lc) = v4;
        }
        __syncthreads();
        float s[4][4];
#pragma unroll
        for (int u = 0; u < 4; u++)
#pragma unroll
            for (int v = 0; v < 4; v++) s[u][v] = 0.f;
#pragma unroll 8
        for (int d = 0; d < 128; d++) {
            float a0 = sQt[d * 65 + ci + 0], a1 = sQt[d * 65 + ci + 1];
            float a2 = sQt[d * 65 + ci + 2], a3 = sQt[d * 65 + ci + 3];
            float b0 = sKt[d * 65 + cj + 0], b1 = sKt[d * 65 + cj + 1];
            float b2 = sKt[d * 65 + cj + 2], b3 = sKt[d * 65 + cj + 3];
            s[0][0] += a0 * b0; s[0][1] += a0 * b1; s[0][2] += a0 * b2; s[0][3] += a0 * b3;
            s[1][0] += a1 * b0; s[1][1] += a1 * b1; s[1][2] += a1 * b2; s[1][3] += a1 * b3;
            s[2][0] += a2 * b0; s[2][1] += a2 * b1; s[2][2] += a2 * b2; s[2][3] += a2 * b3;
            s[3][0] += a3 * b0; s[3][1] += a3 * b1; s[3][2] += a3 * b2; s[3][3] += a3 * b3;
        }
        bool diag = (kb == qt);
#pragma unroll
        for (int u = 0; u < 4; u++)
#pragma unroll
            for (int v = 0; v < 4; v++) {
                float e;
                if (diag && (kb * 64 + cj + v > qbase + ci + u)) {
                    e = 0.0f;   // reference contributes exp(-30)~9e-14: negligible
                } else {
                    float z = s[u][v] * scale - rm[u];
                    z = fminf(fmaxf(z, -30.0f), 0.0f);
                    e = pwl_exp_f(z);
                }
                sE[(ci + u) * 68 + cj + v] = e;
            }
        __syncthreads();
        if (tid < 64) {
            float ssum = rowsum[tid];
            for (int j = 0; j < 64; j++) ssum += sE[tid * 68 + j];
            rowsum[tid] = ssum;
        }
#pragma unroll 4
        for (int kk = 0; kk < 64; kk++) {
            float e0 = sE[(ci + 0) * 68 + kk];
            float e1 = sE[(ci + 1) * 68 + kk];
            float e2 = sE[(ci + 2) * 68 + kk];
            float e3 = sE[(ci + 3) * 68 + kk];
            const float* vr = sV + kk * 132 + (tx << 3);
            float4 va = *(const float4*)(vr);
            float4 vb = *(const float4*)(vr + 4);
            float vv[8] = {va.x, va.y, va.z, va.w, vb.x, vb.y, vb.z, vb.w};
#pragma unroll
            for (int j = 0; j < 8; j++) {
                o[0][j] += e0 * vv[j];
                o[1][j] += e1 * vv[j];
                o[2][j] += e2 * vv[j];
                o[3][j] += e3 * vv[j];
            }
        }
    }
    __syncthreads();
#pragma unroll
    for (int u = 0; u < 4; u++) {
        float inv = pwl_inv_f(rowsum[ci + u]);
        float* op = att + (size_t)(bb * TSEQ + qbase + ci + u) * D_MODEL + h * HD + (tx << 3);
        float r[8];
#pragma unroll
        for (int j = 0; j < 8; j++) r[j] = o[u][j] * inv;
        *(float4*)(op)     = make_float4(r[0], r[1], r[2], r[3]);
        *(float4*)(op + 4) = make_float4(r[4], r[5], r[6], r[7]);
    }
}

// ---------------- host launcher ----------------
extern "C" void kernel_launch(void* const* d_in, const int* in_sizes, int n_in,
                              void* d_out, int out_size)
{
    (void)in_sizes; (void)n_in; (void)out_size;
    const float* x      = (const float*)d_in[0];
    const float* ln1w   = (const float*)d_in[1];
    const float* ln1b   = (const float*)d_in[2];
    const float* ln2w   = (const float*)d_in[3];
    const float* ln2b   = (const float*)d_in[4];
    const float* cattw  = (const float*)d_in[5];
    const float* cattb  = (const float*)d_in[6];
    const float* cprojw = (const float*)d_in[7];
    const float* cprojb = (const float*)d_in[8];
    const float* fcw    = (const float*)d_in[9];
    const float* fcb    = (const float*)d_in[10];
    const float* projw  = (const float*)d_in[11];
    const float* projb  = (const float*)d_in[12];
    float* out = (float*)d_out;

    float *xn, *qkvb, *attb, *x1b, *hb;
    cudaGetSymbolAddress((void**)&xn,   g_xn);
    cudaGetSymbolAddress((void**)&qkvb, g_qkv);
    cudaGetSymbolAddress((void**)&attb, g_att);
    cudaGetSymbolAddress((void**)&x1b,  g_x1);
    cudaGetSymbolAddress((void**)&hb,   g_h);

    cudaFuncSetAttribute(attn_kernel, cudaFuncAttributeMaxDynamicSharedMemorySize,
                         ATT_SMEM_BYTES);

    init_tables_kernel<<<1, 512>>>();

    // x -> ln1 -> qkv
    ln_kernel<<<NTOK, 256>>>(x, ln1w, ln1b, xn);
    {
        dim3 g(D3 / 128, NTOK / 128);
        gemm_kernel<0><<<g, 256>>>(xn, cattw, cattb, nullptr, qkvb, NTOK, D3, D_MODEL);
    }
    // attention
    {
        dim3 g(TSEQ / 64, NHEAD, NBATCH);
        attn_kernel<<<g, 256, ATT_SMEM_BYTES>>>(qkvb, attb);
    }
    // x1 = x + att @ c_proj + b
    {
        dim3 g(D_MODEL / 128, NTOK / 128);
        gemm_kernel<2><<<g, 256>>>(attb, cprojw, cprojb, x, x1b, NTOK, D_MODEL, D_MODEL);
    }
    // ln2 -> h = gelu(fc)
    ln_kernel<<<NTOK, 256>>>(x1b, ln2w, ln2b, xn);
    {
        dim3 g(DFF / 128, NTOK / 128);
        gemm_kernel<1><<<g, 256>>>(xn, fcw, fcb, nullptr, hb, NTOK, DFF, D_MODEL);
    }
    // out = x1 + h @ proj + b
    {
        dim3 g(D_MODEL / 128, NTOK / 128);
        gemm_kernel<2><<<g, 256>>>(hb, projw, projb, x1b, out, NTOK, D_MODEL, DFF);
    }
}

// round 7
// speedup vs baseline: 1.8488x; 1.8488x over previous
#include <cuda_runtime.h>
#include <cuda_bf16.h>
#include <math.h>
#include <stdint.h>

// ---------------- problem constants ----------------
#define D_MODEL 2048
#define D3      6144      // 3*D
#define DFF     8192      // 4*D
#define TSEQ    1024
#define NBATCH  2
#define NTOK    2048      // B*T
#define NHEAD   16
#define HD      128

// ---------------- scratch (device globals; no allocations allowed) ----------------
static __device__ __align__(128) float g_xn [NTOK * D_MODEL];
static __device__ __align__(128) float g_qkv[NTOK * D3];
static __device__ __align__(128) float g_att[NTOK * D_MODEL];
static __device__ __align__(128) float g_x1 [NTOK * D_MODEL];
static __device__ __align__(128) float g_h  [NTOK * DFF];

// pre-transposed + hi/lo decomposed weights: layout [N][K] bf16
static __device__ __align__(128) __nv_bfloat16 g_wqkv_h [D3  * D_MODEL];
static __device__ __align__(128) __nv_bfloat16 g_wqkv_l [D3  * D_MODEL];
static __device__ __align__(128) __nv_bfloat16 g_wproj_h[D_MODEL * D_MODEL];
static __device__ __align__(128) __nv_bfloat16 g_wproj_l[D_MODEL * D_MODEL];
static __device__ __align__(128) __nv_bfloat16 g_wfc_h  [DFF * D_MODEL];
static __device__ __align__(128) __nv_bfloat16 g_wfc_l  [DFF * D_MODEL];
static __device__ __align__(128) __nv_bfloat16 g_wmp_h  [D_MODEL * DFF];
static __device__ __align__(128) __nv_bfloat16 g_wmp_l  [D_MODEL * DFF];

// ---------------- PWL surrogate tables ----------------
static __device__ float g_gx[512], g_gy[512], g_gs[512];
static __device__ float g_ex[512], g_ey[512], g_es[512];
static __device__ float g_ix[512], g_iy[512], g_is[512];
static __device__ float g_rx[512], g_ry[512], g_rs[512];

__global__ void init_tables_kernel()
{
    int i = threadIdx.x;
    {
        double t = -10.0 + 20.0 * (double)i / 511.0;
        float x = (float)t;
        g_gx[i] = x;
        float inner = x + 0.044715f * x * x * x;
        double y = 0.5 * (double)x * (1.0 + tanh(0.7978845608028653559 * (double)inner));
        g_gy[i] = (float)y;
    }
    {
        double t = -30.0 + 30.0 * (double)i / 511.0;
        float x = (float)t;
        g_ex[i] = x;
        g_ey[i] = (float)exp((double)x);
    }
    {
        double lg = -3.0 + (log10(4096.0) + 3.0) * (double)i / 511.0;
        float x = (float)pow(10.0, lg);
        g_ix[i] = x;
        g_iy[i] = 1.0f / x;
    }
    {
        double lg = -6.0 + 8.0 * (double)i / 511.0;
        float x = (float)pow(10.0, lg);
        g_rx[i] = x;
        g_ry[i] = 1.0f / sqrtf(x);
    }
    __syncthreads();
    if (i < 511) {
        g_gs[i] = (g_gy[i + 1] - g_gy[i]) / (g_gx[i + 1] - g_gx[i]);
        g_es[i] = (g_ey[i + 1] - g_ey[i]) / (g_ex[i + 1] - g_ex[i]);
        g_is[i] = (g_iy[i + 1] - g_iy[i]) / (g_ix[i + 1] - g_ix[i]);
        g_rs[i] = (g_ry[i + 1] - g_ry[i]) / (g_rx[i + 1] - g_rx[i]);
    }
}

// ---------------- interp helpers ----------------
__device__ __forceinline__ float pwl_seg(float x, const float* xp, const float* fp,
                                         const float* sl, int i)
{
    i = min(max(i, 0), 510);
    while (i > 0 && x < xp[i]) --i;
    while (i < 510 && x >= xp[i + 1]) ++i;
    return fp[i] + (x - xp[i]) * sl[i];
}
__device__ __forceinline__ float pwl_gelu_f(float x)
{
    if (x <= g_gx[0])   return g_gy[0];
    if (x >= g_gx[511]) return g_gy[511];
    return pwl_seg(x, g_gx, g_gy, g_gs, (int)((x + 10.0f) * (511.0f / 20.0f)));
}
__device__ __forceinline__ float pwl_exp_f(float x)
{
    if (x <= g_ex[0])   return g_ey[0];
    if (x >= g_ex[511]) return g_ey[511];
    return pwl_seg(x, g_ex, g_ey, g_es, (int)((x + 30.0f) * (511.0f / 30.0f)));
}
__device__ __forceinline__ float pwl_inv_f(float x)
{
    if (x <= g_ix[0])   return g_iy[0];
    if (x >= g_ix[511]) return g_iy[511];
    int i = (int)((log2f(x) + 9.965784284662087f) * 23.263455f);
    return pwl_seg(x, g_ix, g_iy, g_is, i);
}
__device__ __forceinline__ float pwl_rsqrt_f(float x)
{
    if (x <= g_rx[0])   return g_ry[0];
    if (x >= g_rx[511]) return g_ry[511];
    int i = (int)((log2f(x) + 19.931568569324174f) * 19.228312f);
    return pwl_seg(x, g_rx, g_ry, g_rs, i);
}

// ---------------- warp-level mma helpers (sm_80-era PTX; valid on plain sm_103) ----
__device__ __forceinline__ uint32_t smem_u32(const void* p)
{
    uint32_t a;
    asm("{ .reg .u64 t; cvta.to.shared.u64 t, %1; cvt.u32.u64 %0, t; }" : "=r"(a) : "l"(p));
    return a;
}

__device__ __forceinline__ void ldsm_x4(uint32_t* r, uint32_t addr)
{
    asm volatile("ldmatrix.sync.aligned.m8n8.x4.shared.b16 {%0,%1,%2,%3}, [%4];"
                 : "=r"(r[0]), "=r"(r[1]), "=r"(r[2]), "=r"(r[3]) : "r"(addr));
}

__device__ __forceinline__ void mma16816(float* c, const uint32_t* a, uint32_t b0, uint32_t b1)
{
    asm volatile(
        "mma.sync.aligned.m16n8k16.row.col.f32.bf16.bf16.f32 "
        "{%0,%1,%2,%3}, {%4,%5,%6,%7}, {%8,%9}, {%0,%1,%2,%3};"
        : "+f"(c[0]), "+f"(c[1]), "+f"(c[2]), "+f"(c[3])
        : "r"(a[0]), "r"(a[1]), "r"(a[2]), "r"(a[3]), "r"(b0), "r"(b1));
}

union BF2U { __nv_bfloat162 h; uint32_t u; };

// ---------------- weight prep: W[K][N] fp32 -> hi/lo bf16 [N][K] ----------------
__global__ void __launch_bounds__(256) prep_w_kernel(const float* __restrict__ W,
                                                     __nv_bfloat16* __restrict__ hi,
                                                     __nv_bfloat16* __restrict__ lo,
                                                     int K, int N)
{
    __shared__ float ts[32][33];
    int nb = blockIdx.x * 32, kb = blockIdx.y * 32;
    int tx = threadIdx.x & 31, ty = threadIdx.x >> 5;   // 32 x 8
#pragma unroll
    for (int j = 0; j < 4; j++)
        ts[ty + 8 * j][tx] = W[(size_t)(kb + ty + 8 * j) * N + nb + tx];
    __syncthreads();
#pragma unroll
    for (int j = 0; j < 4; j++) {
        int n_local = ty + 8 * j;
        float v = ts[tx][n_local];
        __nv_bfloat16 h = __float2bfloat16(v);
        __nv_bfloat16 l = __float2bfloat16(v - __bfloat162float(h));
        size_t o = (size_t)(nb + n_local) * K + kb + tx;
        hi[o] = h;
        lo[o] = l;
    }
}

// ---------------- layernorm ----------------
__global__ void __launch_bounds__(256) ln_kernel(const float* __restrict__ x,
                                                 const float* __restrict__ w,
                                                 const float* __restrict__ b,
                                                 float* __restrict__ out)
{
    __shared__ float red[32];
    int row = blockIdx.x, tid = threadIdx.x;
    const float* xr = x + (size_t)row * D_MODEL;
    int base = tid * 8;
    float4 u0 = *(const float4*)(xr + base);
    float4 u1 = *(const float4*)(xr + base + 4);
    float v[8] = {u0.x, u0.y, u0.z, u0.w, u1.x, u1.y, u1.z, u1.w};

    float s = 0.f;
#pragma unroll
    for (int i = 0; i < 8; i++) s += v[i];
#pragma unroll
    for (int o = 16; o; o >>= 1) s += __shfl_xor_sync(0xffffffffu, s, o);
    int lane = tid & 31, wid = tid >> 5;
    if (lane == 0) red[wid] = s;
    __syncthreads();
    if (tid == 0) {
        float t = 0.f;
#pragma unroll
        for (int i = 0; i < 8; i++) t += red[i];
        red[16] = t * (1.0f / 2048.0f);
    }
    __syncthreads();
    float mu = red[16];

    float sq = 0.f;
#pragma unroll
    for (int i = 0; i < 8; i++) { float d = v[i] - mu; sq += d * d; }
#pragma unroll
    for (int o = 16; o; o >>= 1) sq += __shfl_xor_sync(0xffffffffu, sq, o);
    if (lane == 0) red[wid] = sq;
    __syncthreads();
    if (tid == 0) {
        float t = 0.f;
#pragma unroll
        for (int i = 0; i < 8; i++) t += red[i];
        red[17] = pwl_rsqrt_f(t * (1.0f / 2048.0f) + 1e-5f);
    }
    __syncthreads();
    float inv_std = red[17];

    float4 w0 = *(const float4*)(w + base);
    float4 w1 = *(const float4*)(w + base + 4);
    float4 b0 = *(const float4*)(b + base);
    float4 b1 = *(const float4*)(b + base + 4);
    float wv[8] = {w0.x, w0.y, w0.z, w0.w, w1.x, w1.y, w1.z, w1.w};
    float bv[8] = {b0.x, b0.y, b0.z, b0.w, b1.x, b1.y, b1.z, b1.w};
    float r[8];
#pragma unroll
    for (int i = 0; i < 8; i++) r[i] = (v[i] - mu) * inv_std * wv[i] + bv[i];
    float* op = out + (size_t)row * D_MODEL + base;
    *(float4*)(op)     = make_float4(r[0], r[1], r[2], r[3]);
    *(float4*)(op + 4) = make_float4(r[4], r[5], r[6], r[7]);
}

// ---------------- mma.sync bf16x3 GEMM ----------------
// C[M][N] = A[M][K] (fp32, decomposed on the fly) @ Bt[N][K] (pre-decomposed bf16)
// terms: Ah*Bh + Al*Bh + Ah*Bl  (Al*Bl dropped, ~2^-18 relative)
// Block: 128x128 tile, 256 threads = 8 warps (4 m-groups x 2 n-groups),
// each warp 32x64 = 2x8 m16n8k16 tiles. K-chunk = 32.
// EPI: 0 = bias, 1 = bias + gelu, 2 = bias + residual
#define SSTR 40     // smem row stride in halves (80 bytes; 16B-aligned, ldmatrix-friendly)

template <int EPI>
__global__ void __launch_bounds__(256, 2) gemm_mma_kernel(const float* __restrict__ A,
                                                          const __nv_bfloat16* __restrict__ Bth,
                                                          const __nv_bfloat16* __restrict__ Btl,
                                                          const float* __restrict__ bias,
                                                          const float* __restrict__ R,
                                                          float* __restrict__ C,
                                                          int N, int K)
{
    __shared__ __align__(16) __nv_bfloat16 sAh[128 * SSTR];
    __shared__ __align__(16) __nv_bfloat16 sAl[128 * SSTR];
    __shared__ __align__(16) __nv_bfloat16 sBh[128 * SSTR];
    __shared__ __align__(16) __nv_bfloat16 sBl[128 * SSTR];

    int tid = threadIdx.x;
    int lane = tid & 31, wid = tid >> 5;
    int wm = wid & 3, wn = wid >> 2;
    int bm = blockIdx.y * 128, bn = blockIdx.x * 128;

    uint32_t uAh = smem_u32(sAh), uAl = smem_u32(sAl);
    uint32_t uBh = smem_u32(sBh), uBl = smem_u32(sBl);

    // ldmatrix lane-address offsets (bytes)
    uint32_t offA[2], offB[4];
#pragma unroll
    for (int mt = 0; mt < 2; mt++) {
        int row = wm * 32 + mt * 16 + (lane & 15);
        int col = (lane >> 4) << 3;
        offA[mt] = (uint32_t)(row * SSTR + col) * 2;
    }
#pragma unroll
    for (int ntp = 0; ntp < 4; ntp++) {
        int n = wn * 64 + ntp * 16 + ((lane >> 4) << 3) + (lane & 7);
        int k = ((lane >> 3) & 1) << 3;
        offB[ntp] = (uint32_t)(n * SSTR + k) * 2;
    }

    float acc[2][8][4];
#pragma unroll
    for (int mt = 0; mt < 2; mt++)
#pragma unroll
        for (int nt = 0; nt < 8; nt++)
#pragma unroll
            for (int q = 0; q < 4; q++) acc[mt][nt][q] = 0.f;

    // global load mapping
    int grow = tid >> 1;            // 0..127
    int gseg = tid & 1;             // 0..1
    const float* Ap = A + (size_t)(bm + grow) * K + gseg * 16;
    const char*  Bhp = (const char*)(Bth + (size_t)(bn + grow) * K + gseg * 16);
    const char*  Blp = (const char*)(Btl + (size_t)(bn + grow) * K + gseg * 16);
    uint32_t sArow = (uint32_t)(grow * SSTR + gseg * 16) * 2;   // byte offset in smem tiles

    int nch = K >> 5;
    for (int ch = 0; ch < nch; ch++) {
        // prefetch globals
        float4 pa[4];
#pragma unroll
        for (int j = 0; j < 4; j++) pa[j] = *(const float4*)(Ap + ch * 32 + j * 4);
        uint4 pbh[2], pbl[2];
#pragma unroll
        for (int j = 0; j < 2; j++) {
            pbh[j] = *(const uint4*)(Bhp + (size_t)ch * 64 + j * 16);
            pbl[j] = *(const uint4*)(Blp + (size_t)ch * 64 + j * 16);
        }
        __syncthreads();
        // A: fp32 -> hi/lo bf16
#pragma unroll
        for (int j = 0; j < 4; j++) {
            float4 v = pa[j];
            __nv_bfloat16 hx = __float2bfloat16(v.x);
            __nv_bfloat16 hy = __float2bfloat16(v.y);
            __nv_bfloat16 hz = __float2bfloat16(v.z);
            __nv_bfloat16 hw = __float2bfloat16(v.w);
            __nv_bfloat16 lx = __float2bfloat16(v.x - __bfloat162float(hx));
            __nv_bfloat16 ly = __float2bfloat16(v.y - __bfloat162float(hy));
            __nv_bfloat16 lz = __float2bfloat16(v.z - __bfloat162float(hz));
            __nv_bfloat16 lw = __float2bfloat16(v.w - __bfloat162float(hw));
            BF2U h0, h1, l0, l1;
            h0.h = __halves2bfloat162(hx, hy);
            h1.h = __halves2bfloat162(hz, hw);
            l0.h = __halves2bfloat162(lx, ly);
            l1.h = __halves2bfloat162(lz, lw);
            *(uint2*)((char*)sAh + sArow + j * 8) = make_uint2(h0.u, h1.u);
            *(uint2*)((char*)sAl + sArow + j * 8) = make_uint2(l0.u, l1.u);
        }
#pragma unroll
        for (int j = 0; j < 2; j++) {
            *(uint4*)((char*)sBh + sArow + j * 16) = pbh[j];
            *(uint4*)((char*)sBl + sArow + j * 16) = pbl[j];
        }
        __syncthreads();

#pragma unroll
        for (int ks = 0; ks < 2; ks++) {
            uint32_t ko = ks * 32;   // 16 halves
            uint32_t ah[2][4], al[2][4], bb[4][4];
#pragma unroll
            for (int mt = 0; mt < 2; mt++) {
                ldsm_x4(ah[mt], uAh + offA[mt] + ko);
                ldsm_x4(al[mt], uAl + offA[mt] + ko);
            }
#pragma unroll
            for (int ntp = 0; ntp < 4; ntp++)
                ldsm_x4(bb[ntp], uBh + offB[ntp] + ko);
            // Ah*Bh + Al*Bh
#pragma unroll
            for (int mt = 0; mt < 2; mt++)
#pragma unroll
                for (int nt = 0; nt < 8; nt++) {
                    uint32_t b0 = bb[nt >> 1][(nt & 1) * 2];
                    uint32_t b1 = bb[nt >> 1][(nt & 1) * 2 + 1];
                    mma16816(acc[mt][nt], ah[mt], b0, b1);
                    mma16816(acc[mt][nt], al[mt], b0, b1);
                }
            // Ah*Bl
#pragma unroll
            for (int ntp = 0; ntp < 4; ntp++)
                ldsm_x4(bb[ntp], uBl + offB[ntp] + ko);
#pragma unroll
            for (int mt = 0; mt < 2; mt++)
#pragma unroll
                for (int nt = 0; nt < 8; nt++) {
                    uint32_t b0 = bb[nt >> 1][(nt & 1) * 2];
                    uint32_t b1 = bb[nt >> 1][(nt & 1) * 2 + 1];
                    mma16816(acc[mt][nt], ah[mt], b0, b1);
                }
        }
    }

    // ---- epilogue ----
#pragma unroll
    for (int mt = 0; mt < 2; mt++) {
        int row0 = bm + wm * 32 + mt * 16 + (lane >> 2);
#pragma unroll
        for (int nt = 0; nt < 8; nt++) {
            int col = bn + wn * 64 + nt * 8 + (lane & 3) * 2;
            float2 bv = *(const float2*)(bias + col);
            float v0 = acc[mt][nt][0] + bv.x;
            float v1 = acc[mt][nt][1] + bv.y;
            float v2 = acc[mt][nt][2] + bv.x;
            float v3 = acc[mt][nt][3] + bv.y;
            if (EPI == 1) {
                v0 = pwl_gelu_f(v0); v1 = pwl_gelu_f(v1);
                v2 = pwl_gelu_f(v2); v3 = pwl_gelu_f(v3);
            }
            if (EPI == 2) {
                float2 r0 = *(const float2*)(R + (size_t)row0 * N + col);
                float2 r1 = *(const float2*)(R + (size_t)(row0 + 8) * N + col);
                v0 += r0.x; v1 += r0.y; v2 += r1.x; v3 += r1.y;
            }
            *(float2*)(C + (size_t)row0 * N + col)       = make_float2(v0, v1);
            *(float2*)(C + (size_t)(row0 + 8) * N + col) = make_float2(v2, v3);
        }
    }
}

// ---------------- attention (fp32 two-pass) ----------------
#define ATT_SMEM_FLOATS (128 * 65 * 2 + 64 * 132 + 64 * 68 + 128)
#define ATT_SMEM_BYTES  (ATT_SMEM_FLOATS * 4)

__global__ void __launch_bounds__(256) attn_kernel(const float* __restrict__ qkv,
                                                   float* __restrict__ att)
{
    extern __shared__ float smf[];
    float* sQt    = smf;
    float* sKt    = smf + 128 * 65;
    float* sV     = smf + 2 * 128 * 65;
    float* sE     = sV + 64 * 132;
    float* rowmax = sE + 64 * 68;
    float* rowsum = rowmax + 64;

    int tid = threadIdx.x;
    int qt = blockIdx.x, h = blockIdx.y, bb = blockIdx.z;
    int qbase = qt * 64;
    const float scale = 1.0f / sqrtf(128.0f);

    int lr = tid >> 5;
    int lc = (tid & 31) << 2;

    const float* qp = qkv + (size_t)(bb * TSEQ + qbase) * D3 + h * HD;
    const float* kp = qkv + (size_t)(bb * TSEQ) * D3 + D_MODEL + h * HD;
    const float* vp = qkv + (size_t)(bb * TSEQ) * D3 + 2 * D_MODEL + h * HD;

#pragma unroll
    for (int r = lr; r < 64; r += 8) {
        float4 q4 = *(const float4*)(qp + (size_t)r * D3 + lc);
        sQt[(lc + 0) * 65 + r] = q4.x;
        sQt[(lc + 1) * 65 + r] = q4.y;
        sQt[(lc + 2) * 65 + r] = q4.z;
        sQt[(lc + 3) * 65 + r] = q4.w;
    }
    if (tid < 64) { rowmax[tid] = -INFINITY; rowsum[tid] = 0.0f; }

    int tx = tid & 15, ty = tid >> 4;
    int ci = ty * 4, cj = tx * 4;
    int nkt = qt + 1;

    for (int kb = 0; kb < nkt; kb++) {
        __syncthreads();
#pragma unroll
        for (int r = lr; r < 64; r += 8) {
            float4 k4 = *(const float4*)(kp + (size_t)(kb * 64 + r) * D3 + lc);
            sKt[(lc + 0) * 65 + r] = k4.x;
            sKt[(lc + 1) * 65 + r] = k4.y;
            sKt[(lc + 2) * 65 + r] = k4.z;
            sKt[(lc + 3) * 65 + r] = k4.w;
        }
        __syncthreads();
        float s[4][4];
#pragma unroll
        for (int u = 0; u < 4; u++)
#pragma unroll
            for (int v = 0; v < 4; v++) s[u][v] = 0.f;
#pragma unroll 8
        for (int d = 0; d < 128; d++) {
            float a0 = sQt[d * 65 + ci + 0], a1 = sQt[d * 65 + ci + 1];
            float a2 = sQt[d * 65 + ci + 2], a3 = sQt[d * 65 + ci + 3];
            float b0 = sKt[d * 65 + cj + 0], b1 = sKt[d * 65 + cj + 1];
            float b2 = sKt[d * 65 + cj + 2], b3 = sKt[d * 65 + cj + 3];
            s[0][0] += a0 * b0; s[0][1] += a0 * b1; s[0][2] += a0 * b2; s[0][3] += a0 * b3;
            s[1][0] += a1 * b0; s[1][1] += a1 * b1; s[1][2] += a1 * b2; s[1][3] += a1 * b3;
            s[2][0] += a2 * b0; s[2][1] += a2 * b1; s[2][2] += a2 * b2; s[2][3] += a2 * b3;
            s[3][0] += a3 * b0; s[3][1] += a3 * b1; s[3][2] += a3 * b2; s[3][3] += a3 * b3;
        }
        bool diag = (kb == qt);
#pragma unroll
        for (int u = 0; u < 4; u++)
#pragma unroll
            for (int v = 0; v < 4; v++) {
                float val = s[u][v] * scale;
                if (diag && (kb * 64 + cj + v > qbase + ci + u)) val = -INFINITY;
                sE[(ci + u) * 68 + cj + v] = val;
            }
        __syncthreads();
        if (tid < 64) {
            float m = rowmax[tid];
            for (int j = 0; j < 64; j++) m = fmaxf(m, sE[tid * 68 + j]);
            rowmax[tid] = m;
        }
    }
    __syncthreads();
    float rm[4];
#pragma unroll
    for (int u = 0; u < 4; u++) rm[u] = rowmax[ci + u];

    float o[4][8];
#pragma unroll
    for (int u = 0; u < 4; u++)
#pragma unroll
        for (int j = 0; j < 8; j++) o[u][j] = 0.f;

    for (int kb = 0; kb < nkt; kb++) {
        __syncthreads();
#pragma unroll
        for (int r = lr; r < 64; r += 8) {
            float4 k4 = *(const float4*)(kp + (size_t)(kb * 64 + r) * D3 + lc);
            sKt[(lc + 0) * 65 + r] = k4.x;
            sKt[(lc + 1) * 65 + r] = k4.y;
            sKt[(lc + 2) * 65 + r] = k4.z;
            sKt[(lc + 3) * 65 + r] = k4.w;
            float4 v4 = *(const float4*)(vp + (size_t)(kb * 64 + r) * D3 + lc);
            *(float4*)(sV + r * 132 + lc) = v4;
        }
        __syncthreads();
        float s[4][4];
#pragma unroll
        for (int u = 0; u < 4; u++)
#pragma unroll
            for (int v = 0; v < 4; v++) s[u][v] = 0.f;
#pragma unroll 8
        for (int d = 0; d < 128; d++) {
            float a0 = sQt[d * 65 + ci + 0], a1 = sQt[d * 65 + ci + 1];
            float a2 = sQt[d * 65 + ci + 2], a3 = sQt[d * 65 + ci + 3];
            float b0 = sKt[d * 65 + cj + 0], b1 = sKt[d * 65 + cj + 1];
            float b2 = sKt[d * 65 + cj + 2], b3 = sKt[d * 65 + cj + 3];
            s[0][0] += a0 * b0; s[0][1] += a0 * b1; s[0][2] += a0 * b2; s[0][3] += a0 * b3;
            s[1][0] += a1 * b0; s[1][1] += a1 * b1; s[1][2] += a1 * b2; s[1][3] += a1 * b3;
            s[2][0] += a2 * b0; s[2][1] += a2 * b1; s[2][2] += a2 * b2; s[2][3] += a2 * b3;
            s[3][0] += a3 * b0; s[3][1] += a3 * b1; s[3][2] += a3 * b2; s[3][3] += a3 * b3;
        }
        bool diag = (kb == qt);
#pragma unroll
        for (int u = 0; u < 4; u++)
#pragma unroll
            for (int v = 0; v < 4; v++) {
                float e;
                if (diag && (kb * 64 + cj + v > qbase + ci + u)) {
                    e = 0.0f;
                } else {
                    float z = s[u][v] * scale - rm[u];
                    z = fminf(fmaxf(z, -30.0f), 0.0f);
                    e = pwl_exp_f(z);
                }
                sE[(ci + u) * 68 + cj + v] = e;
            }
        __syncthreads();
        if (tid < 64) {
            float ssum = rowsum[tid];
            for (int j = 0; j < 64; j++) ssum += sE[tid * 68 + j];
            rowsum[tid] = ssum;
        }
#pragma unroll 4
        for (int kk = 0; kk < 64; kk++) {
            float e0 = sE[(ci + 0) * 68 + kk];
            float e1 = sE[(ci + 1) * 68 + kk];
            float e2 = sE[(ci + 2) * 68 + kk];
            float e3 = sE[(ci + 3) * 68 + kk];
            const float* vr = sV + kk * 132 + (tx << 3);
            float4 va = *(const float4*)(vr);
            float4 vb = *(const float4*)(vr + 4);
            float vv[8] = {va.x, va.y, va.z, va.w, vb.x, vb.y, vb.z, vb.w};
#pragma unroll
            for (int j = 0; j < 8; j++) {
                o[0][j] += e0 * vv[j];
                o[1][j] += e1 * vv[j];
                o[2][j] += e2 * vv[j];
                o[3][j] += e3 * vv[j];
            }
        }
    }
    __syncthreads();
#pragma unroll
    for (int u = 0; u < 4; u++) {
        float inv = pwl_inv_f(rowsum[ci + u]);
        float* op = att + (size_t)(bb * TSEQ + qbase + ci + u) * D_MODEL + h * HD + (tx << 3);
        float r[8];
#pragma unroll
        for (int j = 0; j < 8; j++) r[j] = o[u][j] * inv;
        *(float4*)(op)     = make_float4(r[0], r[1], r[2], r[3]);
        *(float4*)(op + 4) = make_float4(r[4], r[5], r[6], r[7]);
    }
}

// ---------------- host launcher ----------------
extern "C" void kernel_launch(void* const* d_in, const int* in_sizes, int n_in,
                              void* d_out, int out_size)
{
    (void)in_sizes; (void)n_in; (void)out_size;
    const float* x      = (const float*)d_in[0];
    const float* ln1w   = (const float*)d_in[1];
    const float* ln1b   = (const float*)d_in[2];
    const float* ln2w   = (const float*)d_in[3];
    const float* ln2b   = (const float*)d_in[4];
    const float* cattw  = (const float*)d_in[5];
    const float* cattb  = (const float*)d_in[6];
    const float* cprojw = (const float*)d_in[7];
    const float* cprojb = (const float*)d_in[8];
    const float* fcw    = (const float*)d_in[9];
    const float* fcb    = (const float*)d_in[10];
    const float* projw  = (const float*)d_in[11];
    const float* projb  = (const float*)d_in[12];
    float* out = (float*)d_out;

    float *xn, *qkvb, *attb, *x1b, *hb;
    cudaGetSymbolAddress((void**)&xn,   g_xn);
    cudaGetSymbolAddress((void**)&qkvb, g_qkv);
    cudaGetSymbolAddress((void**)&attb, g_att);
    cudaGetSymbolAddress((void**)&x1b,  g_x1);
    cudaGetSymbolAddress((void**)&hb,   g_h);

    __nv_bfloat16 *wqh, *wql, *wph, *wpl, *wfh, *wfl, *wmh, *wml;
    cudaGetSymbolAddress((void**)&wqh, g_wqkv_h);
    cudaGetSymbolAddress((void**)&wql, g_wqkv_l);
    cudaGetSymbolAddress((void**)&wph, g_wproj_h);
    cudaGetSymbolAddress((void**)&wpl, g_wproj_l);
    cudaGetSymbolAddress((void**)&wfh, g_wfc_h);
    cudaGetSymbolAddress((void**)&wfl, g_wfc_l);
    cudaGetSymbolAddress((void**)&wmh, g_wmp_h);
    cudaGetSymbolAddress((void**)&wml, g_wmp_l);

    cudaFuncSetAttribute(attn_kernel, cudaFuncAttributeMaxDynamicSharedMemorySize,
                         ATT_SMEM_BYTES);

    init_tables_kernel<<<1, 512>>>();

    // weight prep: transpose + bf16 hi/lo decompose
    prep_w_kernel<<<dim3(D3 / 32,      D_MODEL / 32), 256>>>(cattw,  wqh, wql, D_MODEL, D3);
    prep_w_kernel<<<dim3(D_MODEL / 32, D_MODEL / 32), 256>>>(cprojw, wph, wpl, D_MODEL, D_MODEL);
    prep_w_kernel<<<dim3(DFF / 32,     D_MODEL / 32), 256>>>(fcw,    wfh, wfl, D_MODEL, DFF);
    prep_w_kernel<<<dim3(D_MODEL / 32, DFF / 32),     256>>>(projw,  wmh, wml, DFF, D_MODEL);

    // x -> ln1 -> qkv
    ln_kernel<<<NTOK, 256>>>(x, ln1w, ln1b, xn);
    gemm_mma_kernel<0><<<dim3(D3 / 128, NTOK / 128), 256>>>(
        xn, wqh, wql, cattb, nullptr, qkvb, D3, D_MODEL);

    // attention
    attn_kernel<<<dim3(TSEQ / 64, NHEAD, NBATCH), 256, ATT_SMEM_BYTES>>>(qkvb, attb);

    // x1 = x + att @ c_proj + b
    gemm_mma_kernel<2><<<dim3(D_MODEL / 128, NTOK / 128), 256>>>(
        attb, wph, wpl, cprojb, x, x1b, D_MODEL, D_MODEL);

    // ln2 -> h = gelu(fc)
    ln_kernel<<<NTOK, 256>>>(x1b, ln2w, ln2b, xn);
    gemm_mma_kernel<1><<<dim3(DFF / 128, NTOK / 128), 256>>>(
        xn, wfh, wfl, fcb, nullptr, hb, DFF, D_MODEL);

    // out = x1 + h @ proj + b
    gemm_mma_kernel<2><<<dim3(D_MODEL / 128, NTOK / 128), 256>>>(
        hb, wmh, wml, projb, x1b, out, D_MODEL, DFF);
}

// round 8
// speedup vs baseline: 1.9822x; 1.0721x over previous
#include <cuda_runtime.h>
#include <cuda_bf16.h>
#include <math.h>
#include <stdint.h>

// ---------------- problem constants ----------------
#define D_MODEL 2048
#define D3      6144      // 3*D
#define DFF     8192      // 4*D
#define TSEQ    1024
#define NBATCH  2
#define NTOK    2048      // B*T
#define NHEAD   16
#define HD      128

// ---------------- scratch (device globals; no allocations allowed) ----------------
static __device__ __align__(128) float g_xn [NTOK * D_MODEL];
static __device__ __align__(128) float g_qkv[NTOK * D3];
static __device__ __align__(128) float g_att[NTOK * D_MODEL];
static __device__ __align__(128) float g_x1 [NTOK * D_MODEL];
static __device__ __align__(128) float g_h  [NTOK * DFF];

// pre-transposed + hi/lo decomposed weights: layout [N][K] bf16
static __device__ __align__(128) __nv_bfloat16 g_wqkv_h [D3  * D_MODEL];
static __device__ __align__(128) __nv_bfloat16 g_wqkv_l [D3  * D_MODEL];
static __device__ __align__(128) __nv_bfloat16 g_wproj_h[D_MODEL * D_MODEL];
static __device__ __align__(128) __nv_bfloat16 g_wproj_l[D_MODEL * D_MODEL];
static __device__ __align__(128) __nv_bfloat16 g_wfc_h  [DFF * D_MODEL];
static __device__ __align__(128) __nv_bfloat16 g_wfc_l  [DFF * D_MODEL];
static __device__ __align__(128) __nv_bfloat16 g_wmp_h  [D_MODEL * DFF];
static __device__ __align__(128) __nv_bfloat16 g_wmp_l  [D_MODEL * DFF];

// ---------------- PWL surrogate tables ----------------
static __device__ float g_gx[512], g_gy[512], g_gs[512];
static __device__ float g_ex[512], g_ey[512], g_es[512];
static __device__ float g_ix[512], g_iy[512], g_is[512];
static __device__ float g_rx[512], g_ry[512], g_rs[512];

__global__ void init_tables_kernel()
{
    int i = threadIdx.x;
    {
        double t = -10.0 + 20.0 * (double)i / 511.0;
        float x = (float)t;
        g_gx[i] = x;
        float inner = x + 0.044715f * x * x * x;
        double y = 0.5 * (double)x * (1.0 + tanh(0.7978845608028653559 * (double)inner));
        g_gy[i] = (float)y;
    }
    {
        double t = -30.0 + 30.0 * (double)i / 511.0;
        float x = (float)t;
        g_ex[i] = x;
        g_ey[i] = (float)exp((double)x);
    }
    {
        double lg = -3.0 + (log10(4096.0) + 3.0) * (double)i / 511.0;
        float x = (float)pow(10.0, lg);
        g_ix[i] = x;
        g_iy[i] = 1.0f / x;
    }
    {
        double lg = -6.0 + 8.0 * (double)i / 511.0;
        float x = (float)pow(10.0, lg);
        g_rx[i] = x;
        g_ry[i] = 1.0f / sqrtf(x);
    }
    __syncthreads();
    if (i < 511) {
        g_gs[i] = (g_gy[i + 1] - g_gy[i]) / (g_gx[i + 1] - g_gx[i]);
        g_es[i] = (g_ey[i + 1] - g_ey[i]) / (g_ex[i + 1] - g_ex[i]);
        g_is[i] = (g_iy[i + 1] - g_iy[i]) / (g_ix[i + 1] - g_ix[i]);
        g_rs[i] = (g_ry[i + 1] - g_ry[i]) / (g_rx[i + 1] - g_rx[i]);
    }
}

// ---------------- interp helpers ----------------
__device__ __forceinline__ float pwl_seg(float x, const float* xp, const float* fp,
                                         const float* sl, int i)
{
    i = min(max(i, 0), 510);
    while (i > 0 && x < xp[i]) --i;
    while (i < 510 && x >= xp[i + 1]) ++i;
    return fp[i] + (x - xp[i]) * sl[i];
}
__device__ __forceinline__ float pwl_gelu_f(float x)
{
    if (x <= g_gx[0])   return g_gy[0];
    if (x >= g_gx[511]) return g_gy[511];
    return pwl_seg(x, g_gx, g_gy, g_gs, (int)((x + 10.0f) * (511.0f / 20.0f)));
}
__device__ __forceinline__ float pwl_exp_f(float x)
{
    if (x <= g_ex[0])   return g_ey[0];
    if (x >= g_ex[511]) return g_ey[511];
    return pwl_seg(x, g_ex, g_ey, g_es, (int)((x + 30.0f) * (511.0f / 30.0f)));
}
__device__ __forceinline__ float pwl_inv_f(float x)
{
    if (x <= g_ix[0])   return g_iy[0];
    if (x >= g_ix[511]) return g_iy[511];
    int i = (int)((log2f(x) + 9.965784284662087f) * 23.263455f);
    return pwl_seg(x, g_ix, g_iy, g_is, i);
}
__device__ __forceinline__ float pwl_rsqrt_f(float x)
{
    if (x <= g_rx[0])   return g_ry[0];
    if (x >= g_rx[511]) return g_ry[511];
    int i = (int)((log2f(x) + 19.931568569324174f) * 19.228312f);
    return pwl_seg(x, g_rx, g_ry, g_rs, i);
}

// ---------------- warp-level mma helpers ----------------
__device__ __forceinline__ uint32_t smem_u32(const void* p)
{
    uint32_t a;
    asm("{ .reg .u64 t; cvta.to.shared.u64 t, %1; cvt.u32.u64 %0, t; }" : "=r"(a) : "l"(p));
    return a;
}
__device__ __forceinline__ void ldsm_x4(uint32_t* r, uint32_t addr)
{
    asm volatile("ldmatrix.sync.aligned.m8n8.x4.shared.b16 {%0,%1,%2,%3}, [%4];"
                 : "=r"(r[0]), "=r"(r[1]), "=r"(r[2]), "=r"(r[3]) : "r"(addr));
}
__device__ __forceinline__ void mma16816(float* c, const uint32_t* a, uint32_t b0, uint32_t b1)
{
    asm volatile(
        "mma.sync.aligned.m16n8k16.row.col.f32.bf16.bf16.f32 "
        "{%0,%1,%2,%3}, {%4,%5,%6,%7}, {%8,%9}, {%0,%1,%2,%3};"
        : "+f"(c[0]), "+f"(c[1]), "+f"(c[2]), "+f"(c[3])
        : "r"(a[0]), "r"(a[1]), "r"(a[2]), "r"(a[3]), "r"(b0), "r"(b1));
}

union BF2U { __nv_bfloat162 h; uint32_t u; };

__device__ __forceinline__ void dec2(float a, float b, uint32_t& h, uint32_t& l)
{
    __nv_bfloat16 ha = __float2bfloat16(a), hb = __float2bfloat16(b);
    BF2U H, L;
    H.h = __halves2bfloat162(ha, hb);
    L.h = __halves2bfloat162(__float2bfloat16(a - __bfloat162float(ha)),
                             __float2bfloat16(b - __bfloat162float(hb)));
    h = H.u; l = L.u;
}

// ---------------- weight prep: W[K][N] fp32 -> hi/lo bf16 [N][K] ----------------
__global__ void __launch_bounds__(256) prep_w_kernel(const float* __restrict__ W,
                                                     __nv_bfloat16* __restrict__ hi,
                                                     __nv_bfloat16* __restrict__ lo,
                                                     int K, int N)
{
    __shared__ float ts[32][33];
    int nb = blockIdx.x * 32, kb = blockIdx.y * 32;
    int tx = threadIdx.x & 31, ty = threadIdx.x >> 5;
#pragma unroll
    for (int j = 0; j < 4; j++)
        ts[ty + 8 * j][tx] = W[(size_t)(kb + ty + 8 * j) * N + nb + tx];
    __syncthreads();
#pragma unroll
    for (int j = 0; j < 4; j++) {
        int n_local = ty + 8 * j;
        float v = ts[tx][n_local];
        __nv_bfloat16 h = __float2bfloat16(v);
        __nv_bfloat16 l = __float2bfloat16(v - __bfloat162float(h));
        size_t o = (size_t)(nb + n_local) * K + kb + tx;
        hi[o] = h;
        lo[o] = l;
    }
}

// ---------------- layernorm ----------------
__global__ void __launch_bounds__(256) ln_kernel(const float* __restrict__ x,
                                                 const float* __restrict__ w,
                                                 const float* __restrict__ b,
                                                 float* __restrict__ out)
{
    __shared__ float red[32];
    int row = blockIdx.x, tid = threadIdx.x;
    const float* xr = x + (size_t)row * D_MODEL;
    int base = tid * 8;
    float4 u0 = *(const float4*)(xr + base);
    float4 u1 = *(const float4*)(xr + base + 4);
    float v[8] = {u0.x, u0.y, u0.z, u0.w, u1.x, u1.y, u1.z, u1.w};

    float s = 0.f;
#pragma unroll
    for (int i = 0; i < 8; i++) s += v[i];
#pragma unroll
    for (int o = 16; o; o >>= 1) s += __shfl_xor_sync(0xffffffffu, s, o);
    int lane = tid & 31, wid = tid >> 5;
    if (lane == 0) red[wid] = s;
    __syncthreads();
    if (tid == 0) {
        float t = 0.f;
#pragma unroll
        for (int i = 0; i < 8; i++) t += red[i];
        red[16] = t * (1.0f / 2048.0f);
    }
    __syncthreads();
    float mu = red[16];

    float sq = 0.f;
#pragma unroll
    for (int i = 0; i < 8; i++) { float d = v[i] - mu; sq += d * d; }
#pragma unroll
    for (int o = 16; o; o >>= 1) sq += __shfl_xor_sync(0xffffffffu, sq, o);
    if (lane == 0) red[wid] = sq;
    __syncthreads();
    if (tid == 0) {
        float t = 0.f;
#pragma unroll
        for (int i = 0; i < 8; i++) t += red[i];
        red[17] = pwl_rsqrt_f(t * (1.0f / 2048.0f) + 1e-5f);
    }
    __syncthreads();
    float inv_std = red[17];

    float4 w0 = *(const float4*)(w + base);
    float4 w1 = *(const float4*)(w + base + 4);
    float4 b0 = *(const float4*)(b + base);
    float4 b1 = *(const float4*)(b + base + 4);
    float wv[8] = {w0.x, w0.y, w0.z, w0.w, w1.x, w1.y, w1.z, w1.w};
    float bv[8] = {b0.x, b0.y, b0.z, b0.w, b1.x, b1.y, b1.z, b1.w};
    float r[8];
#pragma unroll
    for (int i = 0; i < 8; i++) r[i] = (v[i] - mu) * inv_std * wv[i] + bv[i];
    float* op = out + (size_t)row * D_MODEL + base;
    *(float4*)(op)     = make_float4(r[0], r[1], r[2], r[3]);
    *(float4*)(op + 4) = make_float4(r[4], r[5], r[6], r[7]);
}

// ---------------- mma.sync bf16x3 GEMM, double-buffered ----------------
#define SSTR 40
#define GTSZ (128 * SSTR * 2)           // one operand tile, bytes (10240)
#define GBUF (4 * GTSZ)                 // Ah, Al, Bh, Bl
#define GEMM_SMEM (2 * GBUF)            // 81920

template <int EPI>
__global__ void __launch_bounds__(256, 2) gemm_mma_kernel(const float* __restrict__ A,
                                                          const __nv_bfloat16* __restrict__ Bth,
                                                          const __nv_bfloat16* __restrict__ Btl,
                                                          const float* __restrict__ bias,
                                                          const float* __restrict__ R,
                                                          float* __restrict__ C,
                                                          int N, int K)
{
    extern __shared__ char smg[];
    int tid = threadIdx.x;
    int lane = tid & 31, wid = tid >> 5;
    int wm = wid & 3, wn = wid >> 2;
    int bm = blockIdx.y * 128, bn = blockIdx.x * 128;

    uint32_t u0 = smem_u32(smg);

    uint32_t offA[2], offB[4];
#pragma unroll
    for (int mt = 0; mt < 2; mt++) {
        int row = wm * 32 + mt * 16 + (lane & 15);
        int col = (lane >> 4) << 3;
        offA[mt] = (uint32_t)(row * SSTR + col) * 2;
    }
#pragma unroll
    for (int ntp = 0; ntp < 4; ntp++) {
        int n = wn * 64 + ntp * 16 + ((lane >> 4) << 3) + (lane & 7);
        int k = ((lane >> 3) & 1) << 3;
        offB[ntp] = (uint32_t)(n * SSTR + k) * 2;
    }

    float acc[2][8][4];
#pragma unroll
    for (int mt = 0; mt < 2; mt++)
#pragma unroll
        for (int nt = 0; nt < 8; nt++)
#pragma unroll
            for (int q = 0; q < 4; q++) acc[mt][nt][q] = 0.f;

    int grow = tid >> 1, gseg = tid & 1;
    const float* Ap = A + (size_t)(bm + grow) * K + gseg * 16;
    const char*  Bhp = (const char*)(Bth + (size_t)(bn + grow) * K + gseg * 16);
    const char*  Blp = (const char*)(Btl + (size_t)(bn + grow) * K + gseg * 16);
    uint32_t sArow = (uint32_t)(grow * SSTR + gseg * 16) * 2;

    float4 pa[4];
    uint4 pbh[2], pbl[2];

#define G_LOAD(ch) do {                                                     \
    _Pragma("unroll")                                                       \
    for (int j = 0; j < 4; j++) pa[j] = *(const float4*)(Ap + (ch) * 32 + j * 4); \
    _Pragma("unroll")                                                       \
    for (int j = 0; j < 2; j++) {                                           \
        pbh[j] = *(const uint4*)(Bhp + (size_t)(ch) * 64 + j * 16);         \
        pbl[j] = *(const uint4*)(Blp + (size_t)(ch) * 64 + j * 16);         \
    } } while (0)

#define G_STORE(buf) do {                                                   \
    char* ah = smg + (buf) * GBUF;                                          \
    char* al = ah + GTSZ;                                                   \
    char* bh = al + GTSZ;                                                   \
    char* bl = bh + GTSZ;                                                   \
    _Pragma("unroll")                                                       \
    for (int j = 0; j < 4; j++) {                                           \
        float4 v = pa[j];                                                   \
        uint32_t h0, l0, h1, l1;                                            \
        dec2(v.x, v.y, h0, l0);                                             \
        dec2(v.z, v.w, h1, l1);                                             \
        *(uint2*)(ah + sArow + j * 8) = make_uint2(h0, h1);                 \
        *(uint2*)(al + sArow + j * 8) = make_uint2(l0, l1);                 \
    }                                                                       \
    _Pragma("unroll")                                                       \
    for (int j = 0; j < 2; j++) {                                           \
        *(uint4*)(bh + sArow + j * 16) = pbh[j];                            \
        *(uint4*)(bl + sArow + j * 16) = pbl[j];                            \
    } } while (0)

    int nch = K >> 5;
    G_LOAD(0);
    G_STORE(0);
    __syncthreads();

    for (int ch = 0; ch < nch; ch++) {
        int cur = ch & 1;
        if (ch + 1 < nch) G_LOAD(ch + 1);

        uint32_t uAh = u0 + cur * GBUF;
        uint32_t uAl = uAh + GTSZ;
        uint32_t uBh = uAl + GTSZ;
        uint32_t uBl = uBh + GTSZ;
#pragma unroll
        for (int ks = 0; ks < 2; ks++) {
            uint32_t ko = ks * 32;
            uint32_t ah[2][4], al[2][4], bb[4][4];
#pragma unroll
            for (int mt = 0; mt < 2; mt++) {
                ldsm_x4(ah[mt], uAh + offA[mt] + ko);
                ldsm_x4(al[mt], uAl + offA[mt] + ko);
            }
#pragma unroll
            for (int ntp = 0; ntp < 4; ntp++)
                ldsm_x4(bb[ntp], uBh + offB[ntp] + ko);
#pragma unroll
            for (int mt = 0; mt < 2; mt++)
#pragma unroll
                for (int nt = 0; nt < 8; nt++) {
                    uint32_t b0 = bb[nt >> 1][(nt & 1) * 2];
                    uint32_t b1 = bb[nt >> 1][(nt & 1) * 2 + 1];
                    mma16816(acc[mt][nt], ah[mt], b0, b1);
                    mma16816(acc[mt][nt], al[mt], b0, b1);
                }
#pragma unroll
            for (int ntp = 0; ntp < 4; ntp++)
                ldsm_x4(bb[ntp], uBl + offB[ntp] + ko);
#pragma unroll
            for (int mt = 0; mt < 2; mt++)
#pragma unroll
                for (int nt = 0; nt < 8; nt++) {
                    uint32_t b0 = bb[nt >> 1][(nt & 1) * 2];
                    uint32_t b1 = bb[nt >> 1][(nt & 1) * 2 + 1];
                    mma16816(acc[mt][nt], ah[mt], b0, b1);
                }
        }
        __syncthreads();
        if (ch + 1 < nch) {
            G_STORE(1 - cur);
            __syncthreads();
        }
    }

    // ---- epilogue ----
#pragma unroll
    for (int mt = 0; mt < 2; mt++) {
        int row0 = bm + wm * 32 + mt * 16 + (lane >> 2);
#pragma unroll
        for (int nt = 0; nt < 8; nt++) {
            int col = bn + wn * 64 + nt * 8 + (lane & 3) * 2;
            float2 bv = *(const float2*)(bias + col);
            float v0 = acc[mt][nt][0] + bv.x;
            float v1 = acc[mt][nt][1] + bv.y;
            float v2 = acc[mt][nt][2] + bv.x;
            float v3 = acc[mt][nt][3] + bv.y;
            if (EPI == 1) {
                v0 = pwl_gelu_f(v0); v1 = pwl_gelu_f(v1);
                v2 = pwl_gelu_f(v2); v3 = pwl_gelu_f(v3);
            }
            if (EPI == 2) {
                float2 r0 = *(const float2*)(R + (size_t)row0 * N + col);
                float2 r1 = *(const float2*)(R + (size_t)(row0 + 8) * N + col);
                v0 += r0.x; v1 += r0.y; v2 += r1.x; v3 += r1.y;
            }
            *(float2*)(C + (size_t)row0 * N + col)       = make_float2(v0, v1);
            *(float2*)(C + (size_t)(row0 + 8) * N + col) = make_float2(v2, v3);
        }
    }
#undef G_LOAD
#undef G_STORE
}

// ---------------- attention: mma.sync bf16x3, two-pass softmax ----------------
#define QSTR 136
#define VSTR 72
#define ESTR 72
#define A_QH   0
#define A_QL   (A_QH + 64 * QSTR * 2)
#define A_KH   (A_QL + 64 * QSTR * 2)
#define A_KL   (A_KH + 64 * QSTR * 2)
#define A_VTH  (A_KL + 64 * QSTR * 2)
#define A_VTL  (A_VTH + 128 * VSTR * 2)
#define A_EH   (A_VTL + 128 * VSTR * 2)
#define A_EL   (A_EH + 64 * ESTR * 2)
#define A_RED  (A_EL + 64 * ESTR * 2)
#define ATT_SMEM (A_RED + 384 * 4)

__global__ void __launch_bounds__(256) attn_mma_kernel(const float* __restrict__ qkv,
                                                       float* __restrict__ att)
{
    extern __shared__ char sma[];
    float* sRed    = (float*)(sma + A_RED);
    float* sMax0   = sRed;          // [2][64]
    float* sRowMax = sRed + 128;    // [64]
    float* sSum0   = sRed + 192;    // [2][64]
    float* sRowSum = sRed + 320;    // [64]

    int tid = threadIdx.x;
    int lane = tid & 31, wid = tid >> 5;
    int wm = wid & 3, wn = wid >> 2;
    int qt = (int)(gridDim.x - 1 - blockIdx.x);
    int h = blockIdx.y, bb = blockIdx.z;
    int qbase = qt * 64;
    const float scale = 0.08838834764831845f;   // 1/sqrt(128)

    uint32_t u0 = smem_u32(sma);
    uint32_t uQh = u0 + A_QH, uQl = u0 + A_QL;
    uint32_t uKh = u0 + A_KH, uKl = u0 + A_KL;
    uint32_t uVh = u0 + A_VTH, uVl = u0 + A_VTL;
    uint32_t uEh = u0 + A_EH, uEl = u0 + A_EL;

    const float* qp = qkv + (size_t)(bb * TSEQ + qbase) * D3 + h * HD;
    const float* kp = qkv + (size_t)(bb * TSEQ) * D3 + D_MODEL + h * HD;
    const float* vp = qkv + (size_t)(bb * TSEQ) * D3 + 2 * D_MODEL + h * HD;

    int lrow = tid >> 2, lcb = (tid & 3) * 32;
    uint32_t sQrow = (uint32_t)(lrow * QSTR + lcb) * 2;

    // ---- load + decompose Q ----
#pragma unroll
    for (int j = 0; j < 8; j++) {
        float4 v = *(const float4*)(qp + (size_t)lrow * D3 + lcb + j * 4);
        uint32_t h0, l0, h1, l1;
        dec2(v.x, v.y, h0, l0);
        dec2(v.z, v.w, h1, l1);
        *(uint2*)(sma + A_QH + sQrow + j * 8) = make_uint2(h0, h1);
        *(uint2*)(sma + A_QL + sQrow + j * 8) = make_uint2(l0, l1);
    }
    if (tid < 64) { sRowMax[tid] = -INFINITY; sRowSum[tid] = 0.0f; }

    // ldsm offsets
    uint32_t offQA = (uint32_t)((wm * 16 + (lane & 15)) * QSTR + ((lane >> 4) << 3)) * 2;
    uint32_t offKB[2], offVB[4];
#pragma unroll
    for (int ntp = 0; ntp < 2; ntp++) {
        int n = wn * 32 + ntp * 16 + ((lane >> 4) << 3) + (lane & 7);
        offKB[ntp] = (uint32_t)(n * QSTR + (((lane >> 3) & 1) << 3)) * 2;
    }
#pragma unroll
    for (int ntp = 0; ntp < 4; ntp++) {
        int n = wn * 64 + ntp * 16 + ((lane >> 4) << 3) + (lane & 7);
        offVB[ntp] = (uint32_t)(n * VSTR + (((lane >> 3) & 1) << 3)) * 2;
    }
    uint32_t offEA = (uint32_t)((wm * 16 + (lane & 15)) * ESTR + ((lane >> 4) << 3)) * 2;

    int nkt = qt + 1;
    int fr = lane >> 2;   // fragment row within m16 (0..7)

    // ================= pass 1: exact row max =================
    for (int kb = 0; kb < nkt; kb++) {
        // load K tile
#pragma unroll
        for (int j = 0; j < 8; j++) {
            float4 v = *(const float4*)(kp + (size_t)(kb * 64 + lrow) * D3 + lcb + j * 4);
            uint32_t h0, l0, h1, l1;
            dec2(v.x, v.y, h0, l0);
            dec2(v.z, v.w, h1, l1);
            *(uint2*)(sma + A_KH + sQrow + j * 8) = make_uint2(h0, h1);
            *(uint2*)(sma + A_KL + sQrow + j * 8) = make_uint2(l0, l1);
        }
        __syncthreads();

        float s[4][4];
#pragma unroll
        for (int nt = 0; nt < 4; nt++)
#pragma unroll
            for (int q = 0; q < 4; q++) s[nt][q] = 0.f;
#pragma unroll
        for (int ks = 0; ks < 8; ks++) {
            uint32_t ko = ks * 32;
            uint32_t qh[4], ql[4], kh[2][4], kl[2][4];
            ldsm_x4(qh, uQh + offQA + ko);
            ldsm_x4(ql, uQl + offQA + ko);
            ldsm_x4(kh[0], uKh + offKB[0] + ko);
            ldsm_x4(kh[1], uKh + offKB[1] + ko);
            ldsm_x4(kl[0], uKl + offKB[0] + ko);
            ldsm_x4(kl[1], uKl + offKB[1] + ko);
#pragma unroll
            for (int nt = 0; nt < 4; nt++) {
                uint32_t b0 = kh[nt >> 1][(nt & 1) * 2];
                uint32_t b1 = kh[nt >> 1][(nt & 1) * 2 + 1];
                mma16816(s[nt], qh, b0, b1);
                mma16816(s[nt], ql, b0, b1);
                uint32_t c0 = kl[nt >> 1][(nt & 1) * 2];
                uint32_t c1 = kl[nt >> 1][(nt & 1) * 2 + 1];
                mma16816(s[nt], qh, c0, c1);
            }
        }
        bool diag = (kb == qt);
        int grow0 = qbase + wm * 16 + fr;
        float mx0 = -INFINITY, mx1 = -INFINITY;
#pragma unroll
        for (int nt = 0; nt < 4; nt++) {
            int gcol = kb * 64 + wn * 32 + nt * 8 + (lane & 3) * 2;
#pragma unroll
            for (int q = 0; q < 4; q++) {
                float val = s[nt][q] * scale;
                int gc = gcol + (q & 1);
                int gr = grow0 + ((q >> 1) << 3);
                if (diag && gc > gr) val = -INFINITY;
                if (q < 2) mx0 = fmaxf(mx0, val);
                else       mx1 = fmaxf(mx1, val);
            }
        }
        mx0 = fmaxf(mx0, __shfl_xor_sync(0xffffffffu, mx0, 1));
        mx0 = fmaxf(mx0, __shfl_xor_sync(0xffffffffu, mx0, 2));
        mx1 = fmaxf(mx1, __shfl_xor_sync(0xffffffffu, mx1, 1));
        mx1 = fmaxf(mx1, __shfl_xor_sync(0xffffffffu, mx1, 2));
        if ((lane & 3) == 0) {
            sMax0[wn * 64 + wm * 16 + fr]     = mx0;
            sMax0[wn * 64 + wm * 16 + fr + 8] = mx1;
        }
        __syncthreads();
        if (tid < 64)
            sRowMax[tid] = fmaxf(sRowMax[tid], fmaxf(sMax0[tid], sMax0[64 + tid]));
    }
    __syncthreads();
    float m0 = sRowMax[wm * 16 + fr];
    float m1 = sRowMax[wm * 16 + fr + 8];

    // ================= pass 2: exp, sum, PV =================
    float o[8][4];
#pragma unroll
    for (int nt = 0; nt < 8; nt++)
#pragma unroll
        for (int q = 0; q < 4; q++) o[nt][q] = 0.f;

    for (int kb = 0; kb < nkt; kb++) {
        __syncthreads();    // prior PV mma done reading sE / sVt / sK
        // load K tile
#pragma unroll
        for (int j = 0; j < 8; j++) {
            float4 v = *(const float4*)(kp + (size_t)(kb * 64 + lrow) * D3 + lcb + j * 4);
            uint32_t h0, l0, h1, l1;
            dec2(v.x, v.y, h0, l0);
            dec2(v.z, v.w, h1, l1);
            *(uint2*)(sma + A_KH + sQrow + j * 8) = make_uint2(h0, h1);
            *(uint2*)(sma + A_KL + sQrow + j * 8) = make_uint2(l0, l1);
        }
        // load V tile, transposed
        {
            int kk = lrow;
#pragma unroll
            for (int j = 0; j < 8; j++) {
                float4 v = *(const float4*)(vp + (size_t)(kb * 64 + kk) * D3 + lcb + j * 4);
                float vv[4] = {v.x, v.y, v.z, v.w};
#pragma unroll
                for (int c = 0; c < 4; c++) {
                    int d = lcb + j * 4 + c;
                    __nv_bfloat16 hh = __float2bfloat16(vv[c]);
                    __nv_bfloat16 ll = __float2bfloat16(vv[c] - __bfloat162float(hh));
                    *(__nv_bfloat16*)(sma + A_VTH + (d * VSTR + kk) * 2) = hh;
                    *(__nv_bfloat16*)(sma + A_VTL + (d * VSTR + kk) * 2) = ll;
                }
            }
        }
        __syncthreads();

        float s[4][4];
#pragma unroll
        for (int nt = 0; nt < 4; nt++)
#pragma unroll
            for (int q = 0; q < 4; q++) s[nt][q] = 0.f;
#pragma unroll
        for (int ks = 0; ks < 8; ks++) {
            uint32_t ko = ks * 32;
            uint32_t qh[4], ql[4], kh[2][4], kl[2][4];
            ldsm_x4(qh, uQh + offQA + ko);
            ldsm_x4(ql, uQl + offQA + ko);
            ldsm_x4(kh[0], uKh + offKB[0] + ko);
            ldsm_x4(kh[1], uKh + offKB[1] + ko);
            ldsm_x4(kl[0], uKl + offKB[0] + ko);
            ldsm_x4(kl[1], uKl + offKB[1] + ko);
#pragma unroll
            for (int nt = 0; nt < 4; nt++) {
                uint32_t b0 = kh[nt >> 1][(nt & 1) * 2];
                uint32_t b1 = kh[nt >> 1][(nt & 1) * 2 + 1];
                mma16816(s[nt], qh, b0, b1);
                mma16816(s[nt], ql, b0, b1);
                uint32_t c0 = kl[nt >> 1][(nt & 1) * 2];
                uint32_t c1 = kl[nt >> 1][(nt & 1) * 2 + 1];
                mma16816(s[nt], qh, c0, c1);
            }
        }
        // exp + sums + write E hi/lo
        bool diag = (kb == qt);
        int grow0 = qbase + wm * 16 + fr;
        float sum0 = 0.f, sum1 = 0.f;
#pragma unroll
        for (int nt = 0; nt < 4; nt++) {
            int colb = wn * 32 + nt * 8 + (lane & 3) * 2;
            int gcol = kb * 64 + colb;
            float e[4];
#pragma unroll
            for (int q = 0; q < 4; q++) {
                int gc = gcol + (q & 1);
                int gr = grow0 + ((q >> 1) << 3);
                if (diag && gc > gr) {
                    e[q] = 0.f;
                } else {
                    float z = s[nt][q] * scale - ((q < 2) ? m0 : m1);
                    z = fminf(fmaxf(z, -30.0f), 0.0f);
                    e[q] = pwl_exp_f(z);
                }
            }
            sum0 += e[0] + e[1];
            sum1 += e[2] + e[3];
            uint32_t h0, l0, h1, l1;
            dec2(e[0], e[1], h0, l0);
            dec2(e[2], e[3], h1, l1);
            int r0 = wm * 16 + fr;
            *(uint32_t*)(sma + A_EH + (r0 * ESTR + colb) * 2)       = h0;
            *(uint32_t*)(sma + A_EL + (r0 * ESTR + colb) * 2)       = l0;
            *(uint32_t*)(sma + A_EH + ((r0 + 8) * ESTR + colb) * 2) = h1;
            *(uint32_t*)(sma + A_EL + ((r0 + 8) * ESTR + colb) * 2) = l1;
        }
        sum0 += __shfl_xor_sync(0xffffffffu, sum0, 1);
        sum0 += __shfl_xor_sync(0xffffffffu, sum0, 2);
        sum1 += __shfl_xor_sync(0xffffffffu, sum1, 1);
        sum1 += __shfl_xor_sync(0xffffffffu, sum1, 2);
        if ((lane & 3) == 0) {
            sSum0[wn * 64 + wm * 16 + fr]     = sum0;
            sSum0[wn * 64 + wm * 16 + fr + 8] = sum1;
        }
        __syncthreads();    // E + sums visible
        if (tid < 64) sRowSum[tid] += sSum0[tid] + sSum0[64 + tid];

        // PV: o += E @ Vt
#pragma unroll
        for (int ks = 0; ks < 4; ks++) {
            uint32_t ko = ks * 32;
            uint32_t eh[4], el[4], vh[4][4], vl[4][4];
            ldsm_x4(eh, uEh + offEA + ko);
            ldsm_x4(el, uEl + offEA + ko);
#pragma unroll
            for (int ntp = 0; ntp < 4; ntp++) {
                ldsm_x4(vh[ntp], uVh + offVB[ntp] + ko);
                ldsm_x4(vl[ntp], uVl + offVB[ntp] + ko);
            }
#pragma unroll
            for (int nt = 0; nt < 8; nt++) {
                uint32_t b0 = vh[nt >> 1][(nt & 1) * 2];
                uint32_t b1 = vh[nt >> 1][(nt & 1) * 2 + 1];
                mma16816(o[nt], eh, b0, b1);
                mma16816(o[nt], el, b0, b1);
                uint32_t c0 = vl[nt >> 1][(nt & 1) * 2];
                uint32_t c1 = vl[nt >> 1][(nt & 1) * 2 + 1];
                mma16816(o[nt], eh, c0, c1);
            }
        }
    }
    __syncthreads();

    // ---- normalize + write ----
    float inv0 = pwl_inv_f(sRowSum[wm * 16 + fr]);
    float inv1 = pwl_inv_f(sRowSum[wm * 16 + fr + 8]);
    size_t row0 = (size_t)(bb * TSEQ + qbase + wm * 16 + fr);
#pragma unroll
    for (int nt = 0; nt < 8; nt++) {
        int col = h * HD + wn * 64 + nt * 8 + (lane & 3) * 2;
        *(float2*)(att + row0 * D_MODEL + col) =
            make_float2(o[nt][0] * inv0, o[nt][1] * inv0);
        *(float2*)(att + (row0 + 8) * D_MODEL + col) =
            make_float2(o[nt][2] * inv1, o[nt][3] * inv1);
    }
}

// ---------------- host launcher ----------------
extern "C" void kernel_launch(void* const* d_in, const int* in_sizes, int n_in,
                              void* d_out, int out_size)
{
    (void)in_sizes; (void)n_in; (void)out_size;
    const float* x      = (const float*)d_in[0];
    const float* ln1w   = (const float*)d_in[1];
    const float* ln1b   = (const float*)d_in[2];
    const float* ln2w   = (const float*)d_in[3];
    const float* ln2b   = (const float*)d_in[4];
    const float* cattw  = (const float*)d_in[5];
    const float* cattb  = (const float*)d_in[6];
    const float* cprojw = (const float*)d_in[7];
    const float* cprojb = (const float*)d_in[8];
    const float* fcw    = (const float*)d_in[9];
    const float* fcb    = (const float*)d_in[10];
    const float* projw  = (const float*)d_in[11];
    const float* projb  = (const float*)d_in[12];
    float* out = (float*)d_out;

    float *xn, *qkvb, *attb, *x1b, *hb;
    cudaGetSymbolAddress((void**)&xn,   g_xn);
    cudaGetSymbolAddress((void**)&qkvb, g_qkv);
    cudaGetSymbolAddress((void**)&attb, g_att);
    cudaGetSymbolAddress((void**)&x1b,  g_x1);
    cudaGetSymbolAddress((void**)&hb,   g_h);

    __nv_bfloat16 *wqh, *wql, *wph, *wpl, *wfh, *wfl, *wmh, *wml;
    cudaGetSymbolAddress((void**)&wqh, g_wqkv_h);
    cudaGetSymbolAddress((void**)&wql, g_wqkv_l);
    cudaGetSymbolAddress((void**)&wph, g_wproj_h);
    cudaGetSymbolAddress((void**)&wpl, g_wproj_l);
    cudaGetSymbolAddress((void**)&wfh, g_wfc_h);
    cudaGetSymbolAddress((void**)&wfl, g_wfc_l);
    cudaGetSymbolAddress((void**)&wmh, g_wmp_h);
    cudaGetSymbolAddress((void**)&wml, g_wmp_l);

    cudaFuncSetAttribute(attn_mma_kernel, cudaFuncAttributeMaxDynamicSharedMemorySize,
                         ATT_SMEM);
    cudaFuncSetAttribute(gemm_mma_kernel<0>, cudaFuncAttributeMaxDynamicSharedMemorySize,
                         GEMM_SMEM);
    cudaFuncSetAttribute(gemm_mma_kernel<1>, cudaFuncAttributeMaxDynamicSharedMemorySize,
                         GEMM_SMEM);
    cudaFuncSetAttribute(gemm_mma_kernel<2>, cudaFuncAttributeMaxDynamicSharedMemorySize,
                         GEMM_SMEM);

    init_tables_kernel<<<1, 512>>>();

    prep_w_kernel<<<dim3(D3 / 32,      D_MODEL / 32), 256>>>(cattw,  wqh, wql, D_MODEL, D3);
    prep_w_kernel<<<dim3(D_MODEL / 32, D_MODEL / 32), 256>>>(cprojw, wph, wpl, D_MODEL, D_MODEL);
    prep_w_kernel<<<dim3(DFF / 32,     D_MODEL / 32), 256>>>(fcw,    wfh, wfl, D_MODEL, DFF);
    prep_w_kernel<<<dim3(D_MODEL / 32, DFF / 32),     256>>>(projw,  wmh, wml, DFF, D_MODEL);

    // x -> ln1 -> qkv
    ln_kernel<<<NTOK, 256>>>(x, ln1w, ln1b, xn);
    gemm_mma_kernel<0><<<dim3(D3 / 128, NTOK / 128), 256, GEMM_SMEM>>>(
        xn, wqh, wql, cattb, nullptr, qkvb, D3, D_MODEL);

    // attention
    attn_mma_kernel<<<dim3(TSEQ / 64, NHEAD, NBATCH), 256, ATT_SMEM>>>(qkvb, attb);

    // x1 = x + att @ c_proj + b
    gemm_mma_kernel<2><<<dim3(D_MODEL / 128, NTOK / 128), 256, GEMM_SMEM>>>(
        attb, wph, wpl, cprojb, x, x1b, D_MODEL, D_MODEL);

    // ln2 -> h = gelu(fc)
    ln_kernel<<<NTOK, 256>>>(x1b, ln2w, ln2b, xn);
    gemm_mma_kernel<1><<<dim3(DFF / 128, NTOK / 128), 256, GEMM_SMEM>>>(
        xn, wfh, wfl, fcb, nullptr, hb, DFF, D_MODEL);

    // out = x1 + h @ proj + b
    gemm_mma_kernel<2><<<dim3(D_MODEL / 128, NTOK / 128), 256, GEMM_SMEM>>>(
        hb, wmh, wml, projb, x1b, out, D_MODEL, DFF);
}

// round 10
// speedup vs baseline: 2.1525x; 1.0859x over previous
#include <cuda_runtime.h>
#include <cuda_bf16.h>
#include <math.h>
#include <stdint.h>

// ---------------- problem constants ----------------
#define D_MODEL 2048
#define D3      6144      // 3*D
#define DFF     8192      // 4*D
#define TSEQ    1024
#define NBATCH  2
#define NTOK    2048      // B*T
#define NHEAD   16
#define HD      128

// ---------------- scratch (device globals; no allocations allowed) ----------------
static __device__ __align__(128) float g_x1 [NTOK * D_MODEL];          // fp32 residual

// activations as hi/lo bf16 pairs
static __device__ __align__(128) __nv_bfloat16 g_xn_h [NTOK * D_MODEL];
static __device__ __align__(128) __nv_bfloat16 g_xn_l [NTOK * D_MODEL];
static __device__ __align__(128) __nv_bfloat16 g_qkv_h[NTOK * D3];
static __device__ __align__(128) __nv_bfloat16 g_qkv_l[NTOK * D3];
static __device__ __align__(128) __nv_bfloat16 g_att_h[NTOK * D_MODEL];
static __device__ __align__(128) __nv_bfloat16 g_att_l[NTOK * D_MODEL];
static __device__ __align__(128) __nv_bfloat16 g_hh   [NTOK * DFF];
static __device__ __align__(128) __nv_bfloat16 g_hl   [NTOK * DFF];

// pre-transposed + hi/lo decomposed weights: layout [N][K] bf16
static __device__ __align__(128) __nv_bfloat16 g_wqkv_h [D3  * D_MODEL];
static __device__ __align__(128) __nv_bfloat16 g_wqkv_l [D3  * D_MODEL];
static __device__ __align__(128) __nv_bfloat16 g_wproj_h[D_MODEL * D_MODEL];
static __device__ __align__(128) __nv_bfloat16 g_wproj_l[D_MODEL * D_MODEL];
static __device__ __align__(128) __nv_bfloat16 g_wfc_h  [DFF * D_MODEL];
static __device__ __align__(128) __nv_bfloat16 g_wfc_l  [DFF * D_MODEL];
static __device__ __align__(128) __nv_bfloat16 g_wmp_h  [D_MODEL * DFF];
static __device__ __align__(128) __nv_bfloat16 g_wmp_l  [D_MODEL * DFF];

// ---------------- PWL surrogate tables ----------------
static __device__ float g_gx[512], g_gy[512], g_gs[512];
static __device__ float g_ex[512], g_ey[512], g_es[512];
static __device__ float g_ix[512], g_iy[512], g_is[512];
static __device__ float g_rx[512], g_ry[512], g_rs[512];

__global__ void init_tables_kernel()
{
    int i = threadIdx.x;
    {
        double t = -10.0 + 20.0 * (double)i / 511.0;
        float x = (float)t;
        g_gx[i] = x;
        float inner = x + 0.044715f * x * x * x;
        double y = 0.5 * (double)x * (1.0 + tanh(0.7978845608028653559 * (double)inner));
        g_gy[i] = (float)y;
    }
    {
        double t = -30.0 + 30.0 * (double)i / 511.0;
        float x = (float)t;
        g_ex[i] = x;
        g_ey[i] = (float)exp((double)x);
    }
    {
        double lg = -3.0 + (log10(4096.0) + 3.0) * (double)i / 511.0;
        float x = (float)pow(10.0, lg);
        g_ix[i] = x;
        g_iy[i] = 1.0f / x;
    }
    {
        double lg = -6.0 + 8.0 * (double)i / 511.0;
        float x = (float)pow(10.0, lg);
        g_rx[i] = x;
        g_ry[i] = 1.0f / sqrtf(x);
    }
    __syncthreads();
    if (i < 511) {
        g_gs[i] = (g_gy[i + 1] - g_gy[i]) / (g_gx[i + 1] - g_gx[i]);
        g_es[i] = (g_ey[i + 1] - g_ey[i]) / (g_ex[i + 1] - g_ex[i]);
        g_is[i] = (g_iy[i + 1] - g_iy[i]) / (g_ix[i + 1] - g_ix[i]);
        g_rs[i] = (g_ry[i + 1] - g_ry[i]) / (g_rx[i + 1] - g_rx[i]);
    }
}

// ---------------- interp helpers ----------------
__device__ __forceinline__ float pwl_seg(float x, const float* xp, const float* fp,
                                         const float* sl, int i)
{
    i = min(max(i, 0), 510);
    while (i > 0 && x < xp[i]) --i;
    while (i < 510 && x >= xp[i + 1]) ++i;
    return fp[i] + (x - xp[i]) * sl[i];
}
__device__ __forceinline__ float pwl_gelu_f(float x)
{
    if (x <= g_gx[0])   return g_gy[0];
    if (x >= g_gx[511]) return g_gy[511];
    return pwl_seg(x, g_gx, g_gy, g_gs, (int)((x + 10.0f) * (511.0f / 20.0f)));
}
__device__ __forceinline__ float pwl_exp_f(float x)
{
    if (x <= g_ex[0])   return g_ey[0];
    if (x >= g_ex[511]) return g_ey[511];
    return pwl_seg(x, g_ex, g_ey, g_es, (int)((x + 30.0f) * (511.0f / 30.0f)));
}
__device__ __forceinline__ float pwl_inv_f(float x)
{
    if (x <= g_ix[0])   return g_iy[0];
    if (x >= g_ix[511]) return g_iy[511];
    int i = (int)((log2f(x) + 9.965784284662087f) * 23.263455f);
    return pwl_seg(x, g_ix, g_iy, g_is, i);
}
__device__ __forceinline__ float pwl_rsqrt_f(float x)
{
    if (x <= g_rx[0])   return g_ry[0];
    if (x >= g_rx[511]) return g_ry[511];
    int i = (int)((log2f(x) + 19.931568569324174f) * 19.228312f);
    return pwl_seg(x, g_rx, g_ry, g_rs, i);
}

// ---------------- warp-level mma / async helpers ----------------
__device__ __forceinline__ uint32_t smem_u32(const void* p)
{
    uint32_t a;
    asm("{ .reg .u64 t; cvta.to.shared.u64 t, %1; cvt.u32.u64 %0, t; }" : "=r"(a) : "l"(p));
    return a;
}
__device__ __forceinline__ void ldsm_x4(uint32_t* r, uint32_t addr)
{
    asm volatile("ldmatrix.sync.aligned.m8n8.x4.shared.b16 {%0,%1,%2,%3}, [%4];"
                 : "=r"(r[0]), "=r"(r[1]), "=r"(r[2]), "=r"(r[3]) : "r"(addr));
}
__device__ __forceinline__ void mma16816(float* c, const uint32_t* a, uint32_t b0, uint32_t b1)
{
    asm volatile(
        "mma.sync.aligned.m16n8k16.row.col.f32.bf16.bf16.f32 "
        "{%0,%1,%2,%3}, {%4,%5,%6,%7}, {%8,%9}, {%0,%1,%2,%3};"
        : "+f"(c[0]), "+f"(c[1]), "+f"(c[2]), "+f"(c[3])
        : "r"(a[0]), "r"(a[1]), "r"(a[2]), "r"(a[3]), "r"(b0), "r"(b1));
}
__device__ __forceinline__ void cpa16(uint32_t dst, const void* src)
{
    asm volatile("cp.async.cg.shared.global [%0], [%1], 16;" :: "r"(dst), "l"(src));
}
#define CPA_COMMIT() asm volatile("cp.async.commit_group;" ::: "memory")
#define CPA_WAIT1()  asm volatile("cp.async.wait_group 1;" ::: "memory")
#define CPA_WAIT0()  asm volatile("cp.async.wait_group 0;" ::: "memory")

union BF2U { __nv_bfloat162 h; uint32_t u; };

__device__ __forceinline__ void dec2(float a, float b, uint32_t& h, uint32_t& l)
{
    __nv_bfloat16 ha = __float2bfloat16(a), hb = __float2bfloat16(b);
    BF2U H, L;
    H.h = __halves2bfloat162(ha, hb);
    L.h = __halves2bfloat162(__float2bfloat16(a - __bfloat162float(ha)),
                             __float2bfloat16(b - __bfloat162float(hb)));
    h = H.u; l = L.u;
}

// ---------------- weight prep: W[K][N] fp32 -> hi/lo bf16 [N][K] ----------------
__global__ void __launch_bounds__(256) prep_w_kernel(const float* __restrict__ W,
                                                     __nv_bfloat16* __restrict__ hi,
                                                     __nv_bfloat16* __restrict__ lo,
                                                     int K, int N)
{
    __shared__ float ts[32][33];
    int nb = blockIdx.x * 32, kb = blockIdx.y * 32;
    int tx = threadIdx.x & 31, ty = threadIdx.x >> 5;
#pragma unroll
    for (int j = 0; j < 4; j++)
        ts[ty + 8 * j][tx] = W[(size_t)(kb + ty + 8 * j) * N + nb + tx];
    __syncthreads();
#pragma unroll
    for (int j = 0; j < 4; j++) {
        int n_local = ty + 8 * j;
        float v = ts[tx][n_local];
        __nv_bfloat16 h = __float2bfloat16(v);
        __nv_bfloat16 l = __float2bfloat16(v - __bfloat162float(h));
        size_t o = (size_t)(nb + n_local) * K + kb + tx;
        hi[o] = h;
        lo[o] = l;
    }
}

// ---------------- layernorm: fp32 in -> hi/lo bf16 out ----------------
__global__ void __launch_bounds__(256) ln_kernel(const float* __restrict__ x,
                                                 const float* __restrict__ w,
                                                 const float* __restrict__ b,
                                                 __nv_bfloat16* __restrict__ oh,
                                                 __nv_bfloat16* __restrict__ ol)
{
    __shared__ float red[32];
    int row = blockIdx.x, tid = threadIdx.x;
    const float* xr = x + (size_t)row * D_MODEL;
    int base = tid * 8;
    float4 u0 = *(const float4*)(xr + base);
    float4 u1 = *(const float4*)(xr + base + 4);
    float v[8] = {u0.x, u0.y, u0.z, u0.w, u1.x, u1.y, u1.z, u1.w};

    float s = 0.f;
#pragma unroll
    for (int i = 0; i < 8; i++) s += v[i];
#pragma unroll
    for (int o = 16; o; o >>= 1) s += __shfl_xor_sync(0xffffffffu, s, o);
    int lane = tid & 31, wid = tid >> 5;
    if (lane == 0) red[wid] = s;
    __syncthreads();
    if (tid == 0) {
        float t = 0.f;
#pragma unroll
        for (int i = 0; i < 8; i++) t += red[i];
        red[16] = t * (1.0f / 2048.0f);
    }
    __syncthreads();
    float mu = red[16];

    float sq = 0.f;
#pragma unroll
    for (int i = 0; i < 8; i++) { float d = v[i] - mu; sq += d * d; }
#pragma unroll
    for (int o = 16; o; o >>= 1) sq += __shfl_xor_sync(0xffffffffu, sq, o);
    if (lane == 0) red[wid] = sq;
    __syncthreads();
    if (tid == 0) {
        float t = 0.f;
#pragma unroll
        for (int i = 0; i < 8; i++) t += red[i];
        red[17] = pwl_rsqrt_f(t * (1.0f / 2048.0f) + 1e-5f);
    }
    __syncthreads();
    float inv_std = red[17];

    float4 w0 = *(const float4*)(w + base);
    float4 w1 = *(const float4*)(w + base + 4);
    float4 b0 = *(const float4*)(b + base);
    float4 b1 = *(const float4*)(b + base + 4);
    float wv[8] = {w0.x, w0.y, w0.z, w0.w, w1.x, w1.y, w1.z, w1.w};
    float bv[8] = {b0.x, b0.y, b0.z, b0.w, b1.x, b1.y, b1.z, b1.w};
    float r[8];
#pragma unroll
    for (int i = 0; i < 8; i++) r[i] = (v[i] - mu) * inv_std * wv[i] + bv[i];

    uint32_t hw[4], lw[4];
#pragma unroll
    for (int i = 0; i < 4; i++) dec2(r[i * 2], r[i * 2 + 1], hw[i], lw[i]);
    size_t o = (size_t)row * D_MODEL + base;
    *(uint4*)(oh + o) = make_uint4(hw[0], hw[1], hw[2], hw[3]);
    *(uint4*)(ol + o) = make_uint4(lw[0], lw[1], lw[2], lw[3]);
}

// ---------------- mma.sync bf16x3 GEMM, cp.async 2-stage ----------------
// C = A @ Bt ; all operands bf16 hi/lo pairs, layout [M][K] / [N][K]
// EPI: 0 = bias -> dec2 bf16 out; 1 = bias+gelu -> dec2 bf16 out; 2 = bias+residual -> fp32 out
#define SSTR 40
#define GTSZ (128 * SSTR * 2)           // 10240 bytes per tile
#define GBUF (4 * GTSZ)                 // Ah, Al, Bh, Bl
#define GEMM_SMEM (2 * GBUF)            // 81920

template <int EPI>
__global__ void __launch_bounds__(256, 2) gemm_mma_kernel(const __nv_bfloat16* __restrict__ Ah_,
                                                          const __nv_bfloat16* __restrict__ Al_,
                                                          const __nv_bfloat16* __restrict__ Bh_,
                                                          const __nv_bfloat16* __restrict__ Bl_,
                                                          const float* __restrict__ bias,
                                                          const float* __restrict__ R,
                                                          float* __restrict__ Cf,
                                                          __nv_bfloat16* __restrict__ Ch,
                                                          __nv_bfloat16* __restrict__ Cl,
                                                          int N, int K)
{
    extern __shared__ char smg[];
    int tid = threadIdx.x;
    int lane = tid & 31, wid = tid >> 5;
    int wm = wid & 3, wn = wid >> 2;
    int bm = blockIdx.y * 128, bn = blockIdx.x * 128;

    uint32_t u0 = smem_u32(smg);

    uint32_t offA[2], offB[4];
#pragma unroll
    for (int mt = 0; mt < 2; mt++) {
        int row = wm * 32 + mt * 16 + (lane & 15);
        int col = (lane >> 4) << 3;
        offA[mt] = (uint32_t)(row * SSTR + col) * 2;
    }
#pragma unroll
    for (int ntp = 0; ntp < 4; ntp++) {
        int n = wn * 64 + ntp * 16 + ((lane >> 4) << 3) + (lane & 7);
        int k = ((lane >> 3) & 1) << 3;
        offB[ntp] = (uint32_t)(n * SSTR + k) * 2;
    }

    float acc[2][8][4];
#pragma unroll
    for (int mt = 0; mt < 2; mt++)
#pragma unroll
        for (int nt = 0; nt < 8; nt++)
#pragma unroll
            for (int q = 0; q < 4; q++) acc[mt][nt][q] = 0.f;

    // async loader mapping: row = tid>>1 (0..127), two 16B segs per thread
    int lrow = tid >> 1;
    int lsg  = (tid & 1) * 2;
    const char* pAh = (const char*)(Ah_ + (size_t)(bm + lrow) * K);
    const char* pAl = (const char*)(Al_ + (size_t)(bm + lrow) * K);
    const char* pBh = (const char*)(Bh_ + (size_t)(bn + lrow) * K);
    const char* pBl = (const char*)(Bl_ + (size_t)(bn + lrow) * K);
    uint32_t drow = (uint32_t)(lrow * SSTR) * 2;

#define LOAD_CHUNK(ch, buf) do {                                            \
    uint32_t sb = u0 + (buf) * GBUF + drow;                                 \
    size_t so = (size_t)(ch) * 64;                                          \
    _Pragma("unroll")                                                       \
    for (int j = 0; j < 2; j++) {                                           \
        uint32_t sg = (uint32_t)(lsg + j) * 16;                             \
        cpa16(sb + 0 * GTSZ + sg, pAh + so + sg);                           \
        cpa16(sb + 1 * GTSZ + sg, pAl + so + sg);                           \
        cpa16(sb + 2 * GTSZ + sg, pBh + so + sg);                           \
        cpa16(sb + 3 * GTSZ + sg, pBl + so + sg);                           \
    } } while (0)

    int nch = K >> 5;
    LOAD_CHUNK(0, 0);
    CPA_COMMIT();

    for (int ch = 0; ch < nch; ch++) {
        int cur = ch & 1;
        if (ch + 1 < nch) {
            LOAD_CHUNK(ch + 1, 1 - cur);
            CPA_COMMIT();
            CPA_WAIT1();
        } else {
            CPA_WAIT0();
        }
        __syncthreads();

        uint32_t uAh = u0 + cur * GBUF;
        uint32_t uAl = uAh + GTSZ;
        uint32_t uBh = uAl + GTSZ;
        uint32_t uBl = uBh + GTSZ;
#pragma unroll
        for (int ks = 0; ks < 2; ks++) {
            uint32_t ko = ks * 32;
            uint32_t ah[2][4], al[2][4], bb[4][4];
#pragma unroll
            for (int mt = 0; mt < 2; mt++) {
                ldsm_x4(ah[mt], uAh + offA[mt] + ko);
                ldsm_x4(al[mt], uAl + offA[mt] + ko);
            }
#pragma unroll
            for (int ntp = 0; ntp < 4; ntp++)
                ldsm_x4(bb[ntp], uBh + offB[ntp] + ko);
#pragma unroll
            for (int mt = 0; mt < 2; mt++)
#pragma unroll
                for (int nt = 0; nt < 8; nt++) {
                    uint32_t b0 = bb[nt >> 1][(nt & 1) * 2];
                    uint32_t b1 = bb[nt >> 1][(nt & 1) * 2 + 1];
                    mma16816(acc[mt][nt], ah[mt], b0, b1);
                    mma16816(acc[mt][nt], al[mt], b0, b1);
                }
#pragma unroll
            for (int ntp = 0; ntp < 4; ntp++)
                ldsm_x4(bb[ntp], uBl + offB[ntp] + ko);
#pragma unroll
            for (int mt = 0; mt < 2; mt++)
#pragma unroll
                for (int nt = 0; nt < 8; nt++) {
                    uint32_t b0 = bb[nt >> 1][(nt & 1) * 2];
                    uint32_t b1 = bb[nt >> 1][(nt & 1) * 2 + 1];
                    mma16816(acc[mt][nt], ah[mt], b0, b1);
                }
        }
        __syncthreads();
    }
#undef LOAD_CHUNK

    // ---- epilogue ----
#pragma unroll
    for (int mt = 0; mt < 2; mt++) {
        int row0 = bm + wm * 32 + mt * 16 + (lane >> 2);
#pragma unroll
        for (int nt = 0; nt < 8; nt++) {
            int col = bn + wn * 64 + nt * 8 + (lane & 3) * 2;
            float2 bv = *(const float2*)(bias + col);
            float v0 = acc[mt][nt][0] + bv.x;
            float v1 = acc[mt][nt][1] + bv.y;
            float v2 = acc[mt][nt][2] + bv.x;
            float v3 = acc[mt][nt][3] + bv.y;
            if (EPI == 1) {
                v0 = pwl_gelu_f(v0); v1 = pwl_gelu_f(v1);
                v2 = pwl_gelu_f(v2); v3 = pwl_gelu_f(v3);
            }
            if (EPI == 2) {
                float2 r0 = *(const float2*)(R + (size_t)row0 * N + col);
                float2 r1 = *(const float2*)(R + (size_t)(row0 + 8) * N + col);
                v0 += r0.x; v1 += r0.y; v2 += r1.x; v3 += r1.y;
                *(float2*)(Cf + (size_t)row0 * N + col)       = make_float2(v0, v1);
                *(float2*)(Cf + (size_t)(row0 + 8) * N + col) = make_float2(v2, v3);
            } else {
                uint32_t h0, l0, h1, l1;
                dec2(v0, v1, h0, l0);
                dec2(v2, v3, h1, l1);
                *(uint32_t*)(Ch + (size_t)row0 * N + col)       = h0;
                *(uint32_t*)(Cl + (size_t)row0 * N + col)       = l0;
                *(uint32_t*)(Ch + (size_t)(row0 + 8) * N + col) = h1;
                *(uint32_t*)(Cl + (size_t)(row0 + 8) * N + col) = l1;
            }
        }
    }
}

// ---------------- attention: mma.sync bf16x3, two-pass softmax ----------------
#define QSTR 136
#define VSTR 72
#define ESTR 72
#define A_QH   0
#define A_QL   (A_QH + 64 * QSTR * 2)
#define A_KH   (A_QL + 64 * QSTR * 2)
#define A_KL   (A_KH + 64 * QSTR * 2)
#define A_VTH  (A_KL + 64 * QSTR * 2)
#define A_VTL  (A_VTH + 128 * VSTR * 2)
#define A_EH   (A_VTL + 128 * VSTR * 2)
#define A_EL   (A_EH + 64 * ESTR * 2)
#define A_RED  (A_EL + 64 * ESTR * 2)
#define ATT_SMEM (A_RED + 384 * 4)

__global__ void __launch_bounds__(256) attn_mma_kernel(const __nv_bfloat16* __restrict__ qkvh,
                                                       const __nv_bfloat16* __restrict__ qkvl,
                                                       __nv_bfloat16* __restrict__ atth,
                                                       __nv_bfloat16* __restrict__ attl)
{
    extern __shared__ char sma[];
    float* sRed    = (float*)(sma + A_RED);
    float* sMax0   = sRed;          // [2][64]
    float* sRowMax = sRed + 128;    // [64]
    float* sSum0   = sRed + 192;    // [2][64]
    float* sRowSum = sRed + 320;    // [64]

    int tid = threadIdx.x;
    int lane = tid & 31, wid = tid >> 5;
    int wm = wid & 3, wn = wid >> 2;
    int qt = (int)(gridDim.x - 1 - blockIdx.x);
    int h = blockIdx.y, bb = blockIdx.z;
    int qbase = qt * 64;
    const float scale = 0.08838834764831845f;   // 1/sqrt(128)

    uint32_t u0 = smem_u32(sma);
    uint32_t uQh = u0 + A_QH, uQl = u0 + A_QL;
    uint32_t uKh = u0 + A_KH, uKl = u0 + A_KL;
    uint32_t uVh = u0 + A_VTH, uVl = u0 + A_VTL;
    uint32_t uEh = u0 + A_EH, uEl = u0 + A_EL;

    const __nv_bfloat16* qph = qkvh + (size_t)(bb * TSEQ + qbase) * D3 + h * HD;
    const __nv_bfloat16* qpl = qkvl + (size_t)(bb * TSEQ + qbase) * D3 + h * HD;
    const __nv_bfloat16* kph = qkvh + (size_t)(bb * TSEQ) * D3 + D_MODEL + h * HD;
    const __nv_bfloat16* kpl = qkvl + (size_t)(bb * TSEQ) * D3 + D_MODEL + h * HD;
    const __nv_bfloat16* vph = qkvh + (size_t)(bb * TSEQ) * D3 + 2 * D_MODEL + h * HD;
    const __nv_bfloat16* vpl = qkvl + (size_t)(bb * TSEQ) * D3 + 2 * D_MODEL + h * HD;

    int lrow = tid >> 2, lcb = (tid & 3) * 32;
    uint32_t sQrow = (uint32_t)(lrow * QSTR + lcb) * 2;

    // ---- load Q hi/lo ----
#pragma unroll
    for (int j = 0; j < 4; j++) {
        *(uint4*)(sma + A_QH + sQrow + j * 16) =
            *(const uint4*)(qph + (size_t)lrow * D3 + lcb + j * 8);
        *(uint4*)(sma + A_QL + sQrow + j * 16) =
            *(const uint4*)(qpl + (size_t)lrow * D3 + lcb + j * 8);
    }
    if (tid < 64) { sRowMax[tid] = -INFINITY; sRowSum[tid] = 0.0f; }

    uint32_t offQA = (uint32_t)((wm * 16 + (lane & 15)) * QSTR + ((lane >> 4) << 3)) * 2;
    uint32_t offKB[2], offVB[4];
#pragma unroll
    for (int ntp = 0; ntp < 2; ntp++) {
        int n = wn * 32 + ntp * 16 + ((lane >> 4) << 3) + (lane & 7);
        offKB[ntp] = (uint32_t)(n * QSTR + (((lane >> 3) & 1) << 3)) * 2;
    }
#pragma unroll
    for (int ntp = 0; ntp < 4; ntp++) {
        int n = wn * 64 + ntp * 16 + ((lane >> 4) << 3) + (lane & 7);
        offVB[ntp] = (uint32_t)(n * VSTR + (((lane >> 3) & 1) << 3)) * 2;
    }
    uint32_t offEA = (uint32_t)((wm * 16 + (lane & 15)) * ESTR + ((lane >> 4) << 3)) * 2;

    int nkt = qt + 1;
    int fr = lane >> 2;

    // ================= pass 1: exact row max =================
    for (int kb = 0; kb < nkt; kb++) {
#pragma unroll
        for (int j = 0; j < 4; j++) {
            *(uint4*)(sma + A_KH + sQrow + j * 16) =
                *(const uint4*)(kph + (size_t)(kb * 64 + lrow) * D3 + lcb + j * 8);
            *(uint4*)(sma + A_KL + sQrow + j * 16) =
                *(const uint4*)(kpl + (size_t)(kb * 64 + lrow) * D3 + lcb + j * 8);
        }
        __syncthreads();

        float s[4][4];
#pragma unroll
        for (int nt = 0; nt < 4; nt++)
#pragma unroll
            for (int q = 0; q < 4; q++) s[nt][q] = 0.f;
#pragma unroll
        for (int ks = 0; ks < 8; ks++) {
            uint32_t ko = ks * 32;
            uint32_t qh[4], ql[4], kh[2][4], kl[2][4];
            ldsm_x4(qh, uQh + offQA + ko);
            ldsm_x4(ql, uQl + offQA + ko);
            ldsm_x4(kh[0], uKh + offKB[0] + ko);
            ldsm_x4(kh[1], uKh + offKB[1] + ko);
            ldsm_x4(kl[0], uKl + offKB[0] + ko);
            ldsm_x4(kl[1], uKl + offKB[1] + ko);
#pragma unroll
            for (int nt = 0; nt < 4; nt++) {
                uint32_t b0 = kh[nt >> 1][(nt & 1) * 2];
                uint32_t b1 = kh[nt >> 1][(nt & 1) * 2 + 1];
                mma16816(s[nt], qh, b0, b1);
                mma16816(s[nt], ql, b0, b1);
                uint32_t c0 = kl[nt >> 1][(nt & 1) * 2];
                uint32_t c1 = kl[nt >> 1][(nt & 1) * 2 + 1];
                mma16816(s[nt], qh, c0, c1);
            }
        }
        bool diag = (kb == qt);
        int grow0 = qbase + wm * 16 + fr;
        float mx0 = -INFINITY, mx1 = -INFINITY;
#pragma unroll
        for (int nt = 0; nt < 4; nt++) {
            int gcol = kb * 64 + wn * 32 + nt * 8 + (lane & 3) * 2;
#pragma unroll
            for (int q = 0; q < 4; q++) {
                float val = s[nt][q] * scale;
                int gc = gcol + (q & 1);
                int gr = grow0 + ((q >> 1) << 3);
                if (diag && gc > gr) val = -INFINITY;
                if (q < 2) mx0 = fmaxf(mx0, val);
                else       mx1 = fmaxf(mx1, val);
            }
        }
        mx0 = fmaxf(mx0, __shfl_xor_sync(0xffffffffu, mx0, 1));
        mx0 = fmaxf(mx0, __shfl_xor_sync(0xffffffffu, mx0, 2));
        mx1 = fmaxf(mx1, __shfl_xor_sync(0xffffffffu, mx1, 1));
        mx1 = fmaxf(mx1, __shfl_xor_sync(0xffffffffu, mx1, 2));
        if ((lane & 3) == 0) {
            sMax0[wn * 64 + wm * 16 + fr]     = mx0;
            sMax0[wn * 64 + wm * 16 + fr + 8] = mx1;
        }
        __syncthreads();
        if (tid < 64)
            sRowMax[tid] = fmaxf(sRowMax[tid], fmaxf(sMax0[tid], sMax0[64 + tid]));
    }
    __syncthreads();
    float m0 = sRowMax[wm * 16 + fr];
    float m1 = sRowMax[wm * 16 + fr + 8];

    // ================= pass 2: exp, sum, PV =================
    float o[8][4];
#pragma unroll
    for (int nt = 0; nt < 8; nt++)
#pragma unroll
        for (int q = 0; q < 4; q++) o[nt][q] = 0.f;

    for (int kb = 0; kb < nkt; kb++) {
        __syncthreads();
#pragma unroll
        for (int j = 0; j < 4; j++) {
            *(uint4*)(sma + A_KH + sQrow + j * 16) =
                *(const uint4*)(kph + (size_t)(kb * 64 + lrow) * D3 + lcb + j * 8);
            *(uint4*)(sma + A_KL + sQrow + j * 16) =
                *(const uint4*)(kpl + (size_t)(kb * 64 + lrow) * D3 + lcb + j * 8);
        }
        // V tile, transposed into smem
        {
            int kk = lrow;
#pragma unroll
            for (int j = 0; j < 4; j++) {
                uint4 hv = *(const uint4*)(vph + (size_t)(kb * 64 + kk) * D3 + lcb + j * 8);
                uint4 lv = *(const uint4*)(vpl + (size_t)(kb * 64 + kk) * D3 + lcb + j * 8);
                const uint16_t* hp = (const uint16_t*)&hv;
                const uint16_t* lp = (const uint16_t*)&lv;
#pragma unroll
                for (int c = 0; c < 8; c++) {
                    int d = lcb + j * 8 + c;
                    *(uint16_t*)(sma + A_VTH + (d * VSTR + kk) * 2) = hp[c];
                    *(uint16_t*)(sma + A_VTL + (d * VSTR + kk) * 2) = lp[c];
                }
            }
        }
        __syncthreads();

        float s[4][4];
#pragma unroll
        for (int nt = 0; nt < 4; nt++)
#pragma unroll
            for (int q = 0; q < 4; q++) s[nt][q] = 0.f;
#pragma unroll
        for (int ks = 0; ks < 8; ks++) {
            uint32_t ko = ks * 32;
            uint32_t qh[4], ql[4], kh[2][4], kl[2][4];
            ldsm_x4(qh, uQh + offQA + ko);
            ldsm_x4(ql, uQl + offQA + ko);
            ldsm_x4(kh[0], uKh + offKB[0] + ko);
            ldsm_x4(kh[1], uKh + offKB[1] + ko);
            ldsm_x4(kl[0], uKl + offKB[0] + ko);
            ldsm_x4(kl[1], uKl + offKB[1] + ko);
#pragma unroll
            for (int nt = 0; nt < 4; nt++) {
                uint32_t b0 = kh[nt >> 1][(nt & 1) * 2];
                uint32_t b1 = kh[nt >> 1][(nt & 1) * 2 + 1];
                mma16816(s[nt], qh, b0, b1);
                mma16816(s[nt], ql, b0, b1);
                uint32_t c0 = kl[nt >> 1][(nt & 1) * 2];
                uint32_t c1 = kl[nt >> 1][(nt & 1) * 2 + 1];
                mma16816(s[nt], qh, c0, c1);
            }
        }
        bool diag = (kb == qt);
        int grow0 = qbase + wm * 16 + fr;
        float sum0 = 0.f, sum1 = 0.f;
#pragma unroll
        for (int nt = 0; nt < 4; nt++) {
            int colb = wn * 32 + nt * 8 + (lane & 3) * 2;
            int gcol = kb * 64 + colb;
            float e[4];
#pragma unroll
            for (int q = 0; q < 4; q++) {
                int gc = gcol + (q & 1);
                int gr = grow0 + ((q >> 1) << 3);
                if (diag && gc > gr) {
                    e[q] = 0.f;
                } else {
                    float z = s[nt][q] * scale - ((q < 2) ? m0 : m1);
                    z = fminf(fmaxf(z, -30.0f), 0.0f);
                    e[q] = pwl_exp_f(z);
                }
            }
            sum0 += e[0] + e[1];
            sum1 += e[2] + e[3];
            uint32_t h0, l0, h1, l1;
            dec2(e[0], e[1], h0, l0);
            dec2(e[2], e[3], h1, l1);
            int r0 = wm * 16 + fr;
            *(uint32_t*)(sma + A_EH + (r0 * ESTR + colb) * 2)       = h0;
            *(uint32_t*)(sma + A_EL + (r0 * ESTR + colb) * 2)       = l0;
            *(uint32_t*)(sma + A_EH + ((r0 + 8) * ESTR + colb) * 2) = h1;
            *(uint32_t*)(sma + A_EL + ((r0 + 8) * ESTR + colb) * 2) = l1;
        }
        sum0 += __shfl_xor_sync(0xffffffffu, sum0, 1);
        sum0 += __shfl_xor_sync(0xffffffffu, sum0, 2);
        sum1 += __shfl_xor_sync(0xffffffffu, sum1, 1);
        sum1 += __shfl_xor_sync(0xffffffffu, sum1, 2);
        if ((lane & 3) == 0) {
            sSum0[wn * 64 + wm * 16 + fr]     = sum0;
            sSum0[wn * 64 + wm * 16 + fr + 8] = sum1;
        }
        __syncthreads();
        if (tid < 64) sRowSum[tid] += sSum0[tid] + sSum0[64 + tid];

        // PV: o += E @ Vt
#pragma unroll
        for (int ks = 0; ks < 4; ks++) {
            uint32_t ko = ks * 32;
            uint32_t eh[4], el[4], vh[4][4], vl[4][4];
            ldsm_x4(eh, uEh + offEA + ko);
            ldsm_x4(el, uEl + offEA + ko);
#pragma unroll
            for (int ntp = 0; ntp < 4; ntp++) {
                ldsm_x4(vh[ntp], uVh + offVB[ntp] + ko);
                ldsm_x4(vl[ntp], uVl + offVB[ntp] + ko);
            }
#pragma unroll
            for (int nt = 0; nt < 8; nt++) {
                uint32_t b0 = vh[nt >> 1][(nt & 1) * 2];
                uint32_t b1 = vh[nt >> 1][(nt & 1) * 2 + 1];
                mma16816(o[nt], eh, b0, b1);
                mma16816(o[nt], el, b0, b1);
                uint32_t c0 = vl[nt >> 1][(nt & 1) * 2];
                uint32_t c1 = vl[nt >> 1][(nt & 1) * 2 + 1];
                mma16816(o[nt], eh, c0, c1);
            }
        }
    }
    __syncthreads();

    // ---- normalize + dec2 write ----
    float inv0 = pwl_inv_f(sRowSum[wm * 16 + fr]);
    float inv1 = pwl_inv_f(sRowSum[wm * 16 + fr + 8]);
    size_t row0 = (size_t)(bb * TSEQ + qbase + wm * 16 + fr);
#pragma unroll
    for (int nt = 0; nt < 8; nt++) {
        int col = h * HD + wn * 64 + nt * 8 + (lane & 3) * 2;
        uint32_t h0, l0, h1, l1;
        dec2(o[nt][0] * inv0, o[nt][1] * inv0, h0, l0);
        dec2(o[nt][2] * inv1, o[nt][3] * inv1, h1, l1);
        *(uint32_t*)(atth + row0 * D_MODEL + col)       = h0;
        *(uint32_t*)(attl + row0 * D_MODEL + col)       = l0;
        *(uint32_t*)(atth + (row0 + 8) * D_MODEL + col) = h1;
        *(uint32_t*)(attl + (row0 + 8) * D_MODEL + col) = l1;
    }
}

// ---------------- host launcher ----------------
extern "C" void kernel_launch(void* const* d_in, const int* in_sizes, int n_in,
                              void* d_out, int out_size)
{
    (void)in_sizes; (void)n_in; (void)out_size;
    const float* x      = (const float*)d_in[0];
    const float* ln1w   = (const float*)d_in[1];
    const float* ln1b   = (const float*)d_in[2];
    const float* ln2w   = (const float*)d_in[3];
    const float* ln2b   = (const float*)d_in[4];
    const float* cattw  = (const float*)d_in[5];
    const float* cattb  = (const float*)d_in[6];
    const float* cprojw = (const float*)d_in[7];
    const float* cprojb = (const float*)d_in[8];
    const float* fcw    = (const float*)d_in[9];
    const float* fcb    = (const float*)d_in[10];
    const float* projw  = (const float*)d_in[11];
    const float* projb  = (const float*)d_in[12];
    float* out = (float*)d_out;

    float* x1b;
    cudaGetSymbolAddress((void**)&x1b, g_x1);

    __nv_bfloat16 *xnh, *xnl, *qkh, *qkl, *ath, *atl, *hh, *hl;
    cudaGetSymbolAddress((void**)&xnh, g_xn_h);
    cudaGetSymbolAddress((void**)&xnl, g_xn_l);
    cudaGetSymbolAddress((void**)&qkh, g_qkv_h);
    cudaGetSymbolAddress((void**)&qkl, g_qkv_l);
    cudaGetSymbolAddress((void**)&ath, g_att_h);
    cudaGetSymbolAddress((void**)&atl, g_att_l);
    cudaGetSymbolAddress((void**)&hh,  g_hh);
    cudaGetSymbolAddress((void**)&hl,  g_hl);

    __nv_bfloat16 *wqh, *wql, *wph, *wpl, *wfh, *wfl, *wmh, *wml;
    cudaGetSymbolAddress((void**)&wqh, g_wqkv_h);
    cudaGetSymbolAddress((void**)&wql, g_wqkv_l);
    cudaGetSymbolAddress((void**)&wph, g_wproj_h);
    cudaGetSymbolAddress((void**)&wpl, g_wproj_l);
    cudaGetSymbolAddress((void**)&wfh, g_wfc_h);
    cudaGetSymbolAddress((void**)&wfl, g_wfc_l);
    cudaGetSymbolAddress((void**)&wmh, g_wmp_h);
    cudaGetSymbolAddress((void**)&wml, g_wmp_l);

    cudaFuncSetAttribute(attn_mma_kernel, cudaFuncAttributeMaxDynamicSharedMemorySize,
                         ATT_SMEM);
    cudaFuncSetAttribute(gemm_mma_kernel<0>, cudaFuncAttributeMaxDynamicSharedMemorySize,
                         GEMM_SMEM);
    cudaFuncSetAttribute(gemm_mma_kernel<1>, cudaFuncAttributeMaxDynamicSharedMemorySize,
                         GEMM_SMEM);
    cudaFuncSetAttribute(gemm_mma_kernel<2>, cudaFuncAttributeMaxDynamicSharedMemorySize,
                         GEMM_SMEM);

    init_tables_kernel<<<1, 512>>>();

    prep_w_kernel<<<dim3(D3 / 32,      D_MODEL / 32), 256>>>(cattw,  wqh, wql, D_MODEL, D3);
    prep_w_kernel<<<dim3(D_MODEL / 32, D_MODEL / 32), 256>>>(cprojw, wph, wpl, D_MODEL, D_MODEL);
    prep_w_kernel<<<dim3(DFF / 32,     D_MODEL / 32), 256>>>(fcw,    wfh, wfl, D_MODEL, DFF);
    prep_w_kernel<<<dim3(D_MODEL / 32, DFF / 32),     256>>>(projw,  wmh, wml, DFF, D_MODEL);

    // x -> ln1 -> qkv (bf16 hi/lo out)
    ln_kernel<<<NTOK, 256>>>(x, ln1w, ln1b, xnh, xnl);
    gemm_mma_kernel<0><<<dim3(D3 / 128, NTOK / 128), 256, GEMM_SMEM>>>(
        xnh, xnl, wqh, wql, cattb, nullptr, nullptr, qkh, qkl, D3, D_MODEL);

    // attention (bf16 hi/lo in and out)
    attn_mma_kernel<<<dim3(TSEQ / 64, NHEAD, NBATCH), 256, ATT_SMEM>>>(qkh, qkl, ath, atl);

    // x1 = x + att @ c_proj + b   (fp32 out)
    gemm_mma_kernel<2><<<dim3(D_MODEL / 128, NTOK / 128), 256, GEMM_SMEM>>>(
        ath, atl, wph, wpl, cprojb, x, x1b, nullptr, nullptr, D_MODEL, D_MODEL);

    // ln2 -> h = gelu(fc)  (bf16 hi/lo out)
    ln_kernel<<<NTOK, 256>>>(x1b, ln2w, ln2b, xnh, xnl);
    gemm_mma_kernel<1><<<dim3(DFF / 128, NTOK / 128), 256, GEMM_SMEM>>>(
        xnh, xnl, wfh, wfl, fcb, nullptr, nullptr, hh, hl, DFF, D_MODEL);

    // out = x1 + h @ proj + b  (fp32 out)
    gemm_mma_kernel<2><<<dim3(D_MODEL / 128, NTOK / 128), 256, GEMM_SMEM>>>(
        hh, hl, wmh, wml, projb, x1b, out, nullptr, nullptr, D_MODEL, DFF);
}